// round 12
// baseline (speedup 1.0000x reference)
#include <cuda_runtime.h>
#include <cuda_fp16.h>
#include <math.h>
#include <stdint.h>

#define NB 4
#define SEQL 2048
#define DMODEL 512
#define NHEAD 8
#define HDIM 64
#define WINDOW 256
#define MTOT (NB*SEQL)
#define XSZ ((size_t)MTOT*DMODEL)
#define WSZ ((size_t)DMODEL*DMODEL)

__device__ __align__(16) float  g_pre[MTOT*DMODEL];
__device__ __align__(16) __half g_W16[4*DMODEL*DMODEL];   // W^T fp16, [w][n][k]
__device__ __align__(16) __half g_Q16[MTOT*DMODEL];       // Q has 0.125*log2e folded
__device__ __align__(16) __half g_K16[MTOT*DMODEL];
__device__ __align__(16) __half g_V16[MTOT*DMODEL];
__device__ __align__(16) __half g_C16[MTOT*DMODEL];       // ctx fp16

__device__ __forceinline__ uint32_t smem_u32(const void* p) {
    uint32_t a;
    asm("{ .reg .u64 t; cvta.to.shared.u64 t, %1; cvt.u32.u64 %0, t; }" : "=r"(a) : "l"(p));
    return a;
}
__device__ __forceinline__ void cpa16(uint32_t dst, const void* src) {
    asm volatile("cp.async.cg.shared.global [%0], [%1], 16;" :: "r"(dst), "l"(src));
}
#define CP_COMMIT() asm volatile("cp.async.commit_group;")
#define CP_WAIT(n)  asm volatile("cp.async.wait_group " #n ";")
__device__ __forceinline__ void ldmx4(uint32_t a, uint32_t* r) {
    asm volatile("ldmatrix.sync.aligned.m8n8.x4.shared.b16 {%0,%1,%2,%3}, [%4];"
                 : "=r"(r[0]), "=r"(r[1]), "=r"(r[2]), "=r"(r[3]) : "r"(a));
}
__device__ __forceinline__ void ldmx4t(uint32_t a, uint32_t* r) {
    asm volatile("ldmatrix.sync.aligned.m8n8.x4.trans.shared.b16 {%0,%1,%2,%3}, [%4];"
                 : "=r"(r[0]), "=r"(r[1]), "=r"(r[2]), "=r"(r[3]) : "r"(a));
}
__device__ __forceinline__ void mma16816(float* d, const uint32_t* a, const uint32_t* b) {
    asm volatile("mma.sync.aligned.m16n8k16.row.col.f32.f16.f16.f32 "
                 "{%0,%1,%2,%3}, {%4,%5,%6,%7}, {%8,%9}, {%0,%1,%2,%3};"
                 : "+f"(d[0]), "+f"(d[1]), "+f"(d[2]), "+f"(d[3])
                 : "r"(a[0]), "r"(a[1]), "r"(a[2]), "r"(a[3]), "r"(b[0]), "r"(b[1]));
}
__device__ __forceinline__ uint32_t packhf(float v0, float v1) {
    __half2 h = __floats2half2_rn(v0, v1);
    return *(uint32_t*)&h;
}
__device__ __forceinline__ float ex2(float x) {
    asm("ex2.approx.f32 %0, %0;" : "+f"(x));
    return x;
}

// ---- prep: W^T fp16 (0.125*log2e folded into W_Q) ------------------------------
__global__ __launch_bounds__(256)
void prep_w_kernel(const float* __restrict__ w0, const float* __restrict__ w1,
                   const float* __restrict__ w2, const float* __restrict__ w3)
{
    __shared__ float s[32][33];
    const int wsel = blockIdx.z;
    const float* W = (wsel == 0) ? w0 : (wsel == 1) ? w1 : (wsel == 2) ? w2 : w3;
    const float scale = (wsel == 0) ? 0.125f * 1.44269504f : 1.0f;
    const int k0 = blockIdx.x * 32, n0 = blockIdx.y * 32;
    const int tx = threadIdx.x, ty = threadIdx.y;
    #pragma unroll
    for (int i = 0; i < 4; i++)
        s[ty + 8 * i][tx] = W[(size_t)(k0 + ty + 8 * i) * DMODEL + n0 + tx];
    __syncthreads();
    const size_t base = (size_t)wsel * WSZ;
    #pragma unroll
    for (int i = 0; i < 4; i++) {
        int n = n0 + ty + 8 * i, k = k0 + tx;
        g_W16[base + (size_t)n * DMODEL + k] = __float2half_rn(s[tx][ty + 8 * i] * scale);
    }
}

// ---- QKV GEMM: fp16, BK=64, 2-stage; A loaded fp32 directly ----------------------
#define STGB 32768
__global__ __launch_bounds__(256)
void gemm_qkv(const float* __restrict__ x0, const float* __restrict__ x1,
              const float* __restrict__ x2)
{
    extern __shared__ char dyn[];
    const uint32_t sbu = smem_u32(dyn);
    const int tid = threadIdx.x, wid = tid >> 5, lane = tid & 31;
    const int wm = wid & 1, wn = wid >> 1;
    const int g8 = lane >> 3, r8 = lane & 7;
    const int bx = blockIdx.x, by = blockIdx.y;
    const int wsel = blockIdx.z;
    const float* X = (wsel == 0) ? x0 : (wsel == 1) ? x1 : x2;
    const __half* Bp = g_W16 + (size_t)wsel * WSZ;
    const int arow = by * 128, brow = bx * 128;

    float4 areg[4][2];
    auto ldgA = [&](int k0) {
        #pragma unroll
        for (int i = 0; i < 4; i++) {
            int idx = tid + i * 256;
            int r = idx >> 3, ch = idx & 7;
            const float* src = X + (size_t)(arow + r) * DMODEL + k0 + ch * 8;
            areg[i][0] = *(const float4*)src;
            areg[i][1] = *(const float4*)(src + 4);
        }
    };
    auto stsA = [&](int s) {
        #pragma unroll
        for (int i = 0; i < 4; i++) {
            int idx = tid + i * 256;
            int r = idx >> 3, ch = idx & 7;
            uint4 p;
            p.x = packhf(areg[i][0].x, areg[i][0].y);
            p.y = packhf(areg[i][0].z, areg[i][0].w);
            p.z = packhf(areg[i][1].x, areg[i][1].y);
            p.w = packhf(areg[i][1].z, areg[i][1].w);
            *(uint4*)(dyn + s * STGB + r * 128 + ((ch ^ (r & 7)) << 4)) = p;
        }
    };
    auto cpaB = [&](int s, int k0) {
        uint32_t base = sbu + (uint32_t)s * STGB + 16384u;
        #pragma unroll
        for (int i = 0; i < 4; i++) {
            int idx = tid + i * 256;
            int r = idx >> 3, ch = idx & 7;
            cpa16(base + (uint32_t)r * 128u + (uint32_t)((ch ^ (r & 7)) << 4),
                  Bp + (size_t)(brow + r) * DMODEL + k0 + ch * 8);
        }
    };

    float d[4][4][4];
    #pragma unroll
    for (int mi = 0; mi < 4; mi++)
        #pragma unroll
        for (int ni = 0; ni < 4; ni++)
            #pragma unroll
            for (int q = 0; q < 4; q++) d[mi][ni][q] = 0.0f;

    ldgA(0); stsA(0); cpaB(0, 0); CP_COMMIT();

    for (int c = 0; c < 8; c++) {
        if (c < 7) {
            ldgA((c + 1) * 64);
            cpaB((c + 1) & 1, (c + 1) * 64);
            CP_COMMIT(); CP_WAIT(1);
        } else { CP_WAIT(0); }
        __syncthreads();

        const uint32_t ss = sbu + (uint32_t)(c & 1) * STGB;
        #pragma unroll
        for (int k16 = 0; k16 < 4; k16++) {
            uint32_t ah[4][4], bh[8];
            #pragma unroll
            for (int mi = 0; mi < 4; mi++) {
                int row = wm * 64 + mi * 16 + r8 + (g8 & 1) * 8;
                int ch  = k16 * 2 + (g8 >> 1);
                ldmx4(ss + (uint32_t)row * 128u + (uint32_t)((ch ^ (row & 7)) << 4), ah[mi]);
            }
            #pragma unroll
            for (int np = 0; np < 2; np++) {
                int row = wn * 32 + np * 16 + r8 + (g8 >> 1) * 8;
                int ch  = k16 * 2 + (g8 & 1);
                ldmx4(ss + 16384u + (uint32_t)row * 128u
                         + (uint32_t)((ch ^ (row & 7)) << 4), &bh[np * 4]);
            }
            #pragma unroll
            for (int mi = 0; mi < 4; mi++)
                #pragma unroll
                for (int ni = 0; ni < 4; ni++)
                    mma16816(d[mi][ni], ah[mi], &bh[ni * 2]);
        }
        if (c < 7) stsA((c + 1) & 1);
        __syncthreads();
    }

    __half* dst = (wsel == 0) ? g_Q16 : (wsel == 1) ? g_K16 : g_V16;
    const int rbase = by * 128 + wm * 64 + (lane >> 2);
    const int cbase = bx * 128 + wn * 32 + (lane & 3) * 2;
    #pragma unroll
    for (int mi = 0; mi < 4; mi++)
        #pragma unroll
        for (int ni = 0; ni < 4; ni++) {
            int col = cbase + ni * 8;
            #pragma unroll
            for (int hf = 0; hf < 2; hf++) {
                int row = rbase + mi * 16 + hf * 8;
                *(uint32_t*)(dst + (size_t)row * DMODEL + col) =
                    packhf(d[mi][ni][hf * 2], d[mi][ni][hf * 2 + 1]);
            }
        }
}

// ---- out-proj GEMM: 128x128 tiles, both operands fp16 cp.async, resid epilogue ----
__global__ __launch_bounds__(256)
void gemm_out(const float* __restrict__ resid)
{
    extern __shared__ char dyn[];
    const uint32_t sbu = smem_u32(dyn);
    const int tid = threadIdx.x, wid = tid >> 5, lane = tid & 31;
    const int wm = wid & 1, wn = wid >> 1;
    const int g8 = lane >> 3, r8 = lane & 7;
    const int bx = blockIdx.x, by = blockIdx.y;
    const __half* A = g_C16;
    const __half* Bp = g_W16 + 3 * WSZ;
    const int arow = by * 128, brow = bx * 128;

    auto stage = [&](int s, int k0) {
        uint32_t base = sbu + (uint32_t)s * STGB;
        #pragma unroll
        for (int i = 0; i < 8; i++) {
            int idx = tid + i * 256;
            int mat = idx >> 10, rem = idx & 1023;
            int r = rem >> 3, ch = rem & 7;
            const __half* src = mat ? Bp : A;
            int row = (mat ? brow : arow) + r;
            cpa16(base + (uint32_t)(mat << 14) + (uint32_t)r * 128u
                        + (uint32_t)((ch ^ (r & 7)) << 4),
                  src + (size_t)row * DMODEL + k0 + ch * 8);
        }
    };

    float d[4][4][4];
    #pragma unroll
    for (int mi = 0; mi < 4; mi++)
        #pragma unroll
        for (int ni = 0; ni < 4; ni++)
            #pragma unroll
            for (int q = 0; q < 4; q++) d[mi][ni][q] = 0.0f;

    stage(0, 0); CP_COMMIT();

    for (int c = 0; c < 8; c++) {
        if (c < 7) {
            stage((c + 1) & 1, (c + 1) * 64);
            CP_COMMIT(); CP_WAIT(1);
        } else { CP_WAIT(0); }
        __syncthreads();

        const uint32_t ss = sbu + (uint32_t)(c & 1) * STGB;
        #pragma unroll
        for (int k16 = 0; k16 < 4; k16++) {
            uint32_t ah[4][4], bh[8];
            #pragma unroll
            for (int mi = 0; mi < 4; mi++) {
                int row = wm * 64 + mi * 16 + r8 + (g8 & 1) * 8;
                int ch  = k16 * 2 + (g8 >> 1);
                ldmx4(ss + (uint32_t)row * 128u + (uint32_t)((ch ^ (row & 7)) << 4), ah[mi]);
            }
            #pragma unroll
            for (int np = 0; np < 2; np++) {
                int row = wn * 32 + np * 16 + r8 + (g8 >> 1) * 8;
                int ch  = k16 * 2 + (g8 & 1);
                ldmx4(ss + 16384u + (uint32_t)row * 128u
                         + (uint32_t)((ch ^ (row & 7)) << 4), &bh[np * 4]);
            }
            #pragma unroll
            for (int mi = 0; mi < 4; mi++)
                #pragma unroll
                for (int ni = 0; ni < 4; ni++)
                    mma16816(d[mi][ni], ah[mi], &bh[ni * 2]);
        }
        __syncthreads();
    }

    const int rbase = by * 128 + wm * 64 + (lane >> 2);
    const int cbase = bx * 128 + wn * 32 + (lane & 3) * 2;
    #pragma unroll
    for (int mi = 0; mi < 4; mi++)
        #pragma unroll
        for (int ni = 0; ni < 4; ni++) {
            int col = cbase + ni * 8;
            #pragma unroll
            for (int hf = 0; hf < 2; hf++) {
                int row = rbase + mi * 16 + hf * 8;
                size_t off = (size_t)row * DMODEL + col;
                float2 rv = *(const float2*)(resid + off);
                *(float2*)(g_pre + off) =
                    make_float2(d[mi][ni][hf * 2] + rv.x, d[mi][ni][hf * 2 + 1] + rv.y);
            }
        }
}

// ---- LayerNorm: one block per row -------------------------------------------------
__global__ __launch_bounds__(256)
void ln_kernel(float* __restrict__ out)
{
    __shared__ float red[16];
    const int row = blockIdx.x, tid = threadIdx.x;
    const float* x = g_pre + (size_t)row * DMODEL;
    float v0 = x[tid], v1 = x[tid + 256];
    float s = v0 + v1, sq = v0 * v0 + v1 * v1;
    #pragma unroll
    for (int off = 16; off > 0; off >>= 1) {
        s  += __shfl_xor_sync(0xffffffffu, s, off);
        sq += __shfl_xor_sync(0xffffffffu, sq, off);
    }
    if ((tid & 31) == 0) { red[tid >> 5] = s; red[8 + (tid >> 5)] = sq; }
    __syncthreads();
    float st = 0.0f, sqt = 0.0f;
    #pragma unroll
    for (int w = 0; w < 8; w++) { st += red[w]; sqt += red[8 + w]; }
    float mean = st * (1.0f / DMODEL);
    float var  = sqt * (1.0f / DMODEL) - mean * mean;
    float rstd = rsqrtf(var + 1e-5f);
    out[(size_t)row * DMODEL + tid]       = (v0 - mean) * rstd;
    out[(size_t)row * DMODEL + tid + 256] = (v1 - mean) * rstd;
}

// ---- attention: fp16 flash, banded, fixed-base softmax (MUFU.EX2) ------------------
__device__ __forceinline__ void stage_kv(uint32_t sb, int s, int b, int h,
                                         int krow0, int tid)
{
    const uint32_t base = sb + 8192u + (uint32_t)s * 16384u;
    #pragma unroll
    for (int i = 0; i < 8; i++) {
        int idx = tid + i * 128;
        int mat = idx >> 9, rem = idx & 511;
        int r = rem >> 3, ch = rem & 7;
        const __half* src = (mat ? g_V16 : g_K16)
            + (size_t)(b * SEQL + krow0 + r) * DMODEL + h * HDIM + ch * 8;
        cpa16(base + (uint32_t)mat * 8192u + (uint32_t)r * 128u
                   + (uint32_t)((ch ^ (r & 7)) << 4), src);
    }
}

__global__ __launch_bounds__(128, 3)
void attn_tc()
{
    extern __shared__ char dyn[];
    const uint32_t sb = smem_u32(dyn);
    const int tid = threadIdx.x, wid = tid >> 5, lane = tid & 31;
    const int r8 = lane & 7, g8 = lane >> 3;
    const int qt = blockIdx.x, h = blockIdx.y, b = blockIdx.z;
    const int q0 = qt * 64;

    #pragma unroll
    for (int i = 0; i < 4; i++) {
        int idx = tid + i * 128;
        int r = idx >> 3, ch = idx & 7;
        const __half* src = g_Q16
            + (size_t)(b * SEQL + q0 + r) * DMODEL + h * HDIM + ch * 8;
        cpa16(sb + (uint32_t)r * 128u + (uint32_t)((ch ^ (r & 7)) << 4), src);
    }
    const int kt_lo = (qt >= 4) ? qt - 4 : 0;
    stage_kv(sb, 0, b, h, kt_lo * 64, tid);
    CP_COMMIT(); CP_WAIT(0);
    __syncthreads();

    uint32_t qh[4][4];
    #pragma unroll
    for (int k16 = 0; k16 < 4; k16++) {
        int row = wid * 16 + r8 + (g8 & 1) * 8;
        int ch  = k16 * 2 + (g8 >> 1);
        ldmx4(sb + (uint32_t)row * 128u + (uint32_t)((ch ^ (row & 7)) << 4), qh[k16]);
    }

    float o[8][4];
    #pragma unroll
    for (int ni = 0; ni < 8; ni++)
        #pragma unroll
        for (int c = 0; c < 4; c++) o[ni][c] = 0.0f;
    float l0 = 0.0f, l1 = 0.0f;

    for (int kt = kt_lo; kt <= qt; kt++) {
        const int s = (kt - kt_lo) & 1;
        if (kt < qt) { stage_kv(sb, s ^ 1, b, h, (kt + 1) * 64, tid); CP_COMMIT(); }
        const uint32_t kb = sb + 8192u + (uint32_t)s * 16384u;

        float sc[8][4];
        #pragma unroll
        for (int ni = 0; ni < 8; ni++)
            #pragma unroll
            for (int c = 0; c < 4; c++) sc[ni][c] = 0.0f;

        #pragma unroll
        for (int k16 = 0; k16 < 4; k16++) {
            uint32_t kh[4][4];
            #pragma unroll
            for (int ng = 0; ng < 4; ng++) {
                int row = ng * 16 + r8 + (g8 >> 1) * 8;
                int ch  = k16 * 2 + (g8 & 1);
                ldmx4(kb + (uint32_t)row * 128u + (uint32_t)((ch ^ (row & 7)) << 4), kh[ng]);
            }
            #pragma unroll
            for (int ng = 0; ng < 4; ng++)
                #pragma unroll
                for (int hf = 0; hf < 2; hf++)
                    mma16816(sc[ng * 2 + hf], qh[k16], &kh[ng][hf * 2]);
        }

        const int k0 = kt * 64;
        if (kt == qt || (qt >= 4 && kt == qt - 4)) {
            const bool diag = (kt == qt);
            const int qr0 = q0 + wid * 16 + (lane >> 2);
            #pragma unroll
            for (int ni = 0; ni < 8; ni++) {
                int kj = k0 + ni * 8 + 2 * (lane & 3);
                #pragma unroll
                for (int c = 0; c < 4; c++) {
                    int kcol = kj + (c & 1), qrow = qr0 + (c >> 1) * 8;
                    bool ok = diag ? (kcol <= qrow) : (kcol >= qrow - (WINDOW - 1));
                    if (!ok) sc[ni][c] = -INFINITY;
                }
            }
        }

        #pragma unroll
        for (int ni = 0; ni < 8; ni++) {
            sc[ni][0] = ex2(sc[ni][0]);
            sc[ni][1] = ex2(sc[ni][1]);
            sc[ni][2] = ex2(sc[ni][2]);
            sc[ni][3] = ex2(sc[ni][3]);
            l0 += sc[ni][0] + sc[ni][1];
            l1 += sc[ni][2] + sc[ni][3];
        }

        uint32_t ph[4][4];
        #pragma unroll
        for (int t = 0; t < 4; t++) {
            ph[t][0] = packhf(sc[2*t][0],   sc[2*t][1]);
            ph[t][1] = packhf(sc[2*t][2],   sc[2*t][3]);
            ph[t][2] = packhf(sc[2*t+1][0], sc[2*t+1][1]);
            ph[t][3] = packhf(sc[2*t+1][2], sc[2*t+1][3]);
        }

        const uint32_t vb = kb + 8192u;
        #pragma unroll
        for (int kt16 = 0; kt16 < 4; kt16++) {
            uint32_t vh[4][4];
            #pragma unroll
            for (int ng = 0; ng < 4; ng++) {
                int row = kt16 * 16 + r8 + (g8 & 1) * 8;
                int ch  = ng * 2 + (g8 >> 1);
                ldmx4t(vb + (uint32_t)row * 128u + (uint32_t)((ch ^ (row & 7)) << 4), vh[ng]);
            }
            #pragma unroll
            for (int ng = 0; ng < 4; ng++)
                #pragma unroll
                for (int hf = 0; hf < 2; hf++)
                    mma16816(o[ng * 2 + hf], ph[kt16], &vh[ng][hf * 2]);
        }
        if (kt < qt) { CP_WAIT(0); __syncthreads(); }
    }

    l0 += __shfl_xor_sync(0xffffffffu, l0, 1);
    l0 += __shfl_xor_sync(0xffffffffu, l0, 2);
    l1 += __shfl_xor_sync(0xffffffffu, l1, 1);
    l1 += __shfl_xor_sync(0xffffffffu, l1, 2);

    const float i0 = 1.0f / l0, i1 = 1.0f / l1;
    const int row0 = q0 + wid * 16 + (lane >> 2);
    #pragma unroll
    for (int ni = 0; ni < 8; ni++) {
        int col = h * HDIM + ni * 8 + 2 * (lane & 3);
        size_t o0 = (size_t)(b * SEQL + row0) * DMODEL + col;
        *(uint32_t*)(g_C16 + o0) = packhf(o[ni][0] * i0, o[ni][1] * i0);
        *(uint32_t*)(g_C16 + o0 + 8 * DMODEL) = packhf(o[ni][2] * i1, o[ni][3] * i1);
    }
}

// ---------------------------------------------------------------------------------------
extern "C" void kernel_launch(void* const* d_in, const int* in_sizes, int n_in,
                              void* d_out, int out_size)
{
    const float* iQ = (const float*)d_in[0];
    const float* iK = (const float*)d_in[1];
    const float* iV = (const float*)d_in[2];
    const float* wQ = (const float*)d_in[3];
    const float* wK = (const float*)d_in[4];
    const float* wV = (const float*)d_in[5];
    const float* wF = (const float*)d_in[6];
    float* out = (float*)d_out;

    prep_w_kernel<<<dim3(16, 16, 4), dim3(32, 8)>>>(wQ, wK, wV, wF);

    const int gemm_smem = 2 * STGB;   // 65536
    cudaFuncSetAttribute((const void*)gemm_qkv,
                         cudaFuncAttributeMaxDynamicSharedMemorySize, gemm_smem);
    cudaFuncSetAttribute((const void*)gemm_out,
                         cudaFuncAttributeMaxDynamicSharedMemorySize, gemm_smem);
    cudaFuncSetAttribute((const void*)attn_tc,
                         cudaFuncAttributeMaxDynamicSharedMemorySize, 40960);

    gemm_qkv<<<dim3(4, 64, 3), 256, gemm_smem>>>(iQ, iK, iV);
    attn_tc<<<dim3(SEQL / 64, NHEAD, NB), 128, 40960>>>();
    gemm_out<<<dim3(4, 64), 256, gemm_smem>>>(iQ);
    ln_kernel<<<MTOT, 256>>>(out);
}

// round 13
// speedup vs baseline: 1.0850x; 1.0850x over previous
#include <cuda_runtime.h>
#include <cuda_fp16.h>
#include <math.h>
#include <stdint.h>

#define NB 4
#define SEQL 2048
#define DMODEL 512
#define NHEAD 8
#define HDIM 64
#define WINDOW 256
#define MTOT (NB*SEQL)
#define XSZ ((size_t)MTOT*DMODEL)
#define WSZ ((size_t)DMODEL*DMODEL)

__device__ __align__(16) __half g_W16[4*DMODEL*DMODEL];   // W^T fp16, [w][n][k]
__device__ __align__(16) __half g_Q16[MTOT*DMODEL];       // Q has 0.125*log2e folded
__device__ __align__(16) __half g_K16[MTOT*DMODEL];
__device__ __align__(16) __half g_V16[MTOT*DMODEL];
__device__ __align__(16) __half g_C16[MTOT*DMODEL];       // ctx fp16

__device__ __forceinline__ uint32_t smem_u32(const void* p) {
    uint32_t a;
    asm("{ .reg .u64 t; cvta.to.shared.u64 t, %1; cvt.u32.u64 %0, t; }" : "=r"(a) : "l"(p));
    return a;
}
__device__ __forceinline__ void cpa16(uint32_t dst, const void* src) {
    asm volatile("cp.async.cg.shared.global [%0], [%1], 16;" :: "r"(dst), "l"(src));
}
#define CP_COMMIT() asm volatile("cp.async.commit_group;")
#define CP_WAIT(n)  asm volatile("cp.async.wait_group " #n ";")
__device__ __forceinline__ void ldmx4(uint32_t a, uint32_t* r) {
    asm volatile("ldmatrix.sync.aligned.m8n8.x4.shared.b16 {%0,%1,%2,%3}, [%4];"
                 : "=r"(r[0]), "=r"(r[1]), "=r"(r[2]), "=r"(r[3]) : "r"(a));
}
__device__ __forceinline__ void ldmx4t(uint32_t a, uint32_t* r) {
    asm volatile("ldmatrix.sync.aligned.m8n8.x4.trans.shared.b16 {%0,%1,%2,%3}, [%4];"
                 : "=r"(r[0]), "=r"(r[1]), "=r"(r[2]), "=r"(r[3]) : "r"(a));
}
__device__ __forceinline__ void mma16816(float* d, const uint32_t* a, const uint32_t* b) {
    asm volatile("mma.sync.aligned.m16n8k16.row.col.f32.f16.f16.f32 "
                 "{%0,%1,%2,%3}, {%4,%5,%6,%7}, {%8,%9}, {%0,%1,%2,%3};"
                 : "+f"(d[0]), "+f"(d[1]), "+f"(d[2]), "+f"(d[3])
                 : "r"(a[0]), "r"(a[1]), "r"(a[2]), "r"(a[3]), "r"(b[0]), "r"(b[1]));
}
__device__ __forceinline__ uint32_t packhf(float v0, float v1) {
    __half2 h = __floats2half2_rn(v0, v1);
    return *(uint32_t*)&h;
}
__device__ __forceinline__ float ex2(float x) {
    asm("ex2.approx.f32 %0, %0;" : "+f"(x));
    return x;
}

// ---- prep: W^T fp16 (0.125*log2e folded into W_Q) ------------------------------
__global__ __launch_bounds__(256)
void prep_w_kernel(const float* __restrict__ w0, const float* __restrict__ w1,
                   const float* __restrict__ w2, const float* __restrict__ w3)
{
    __shared__ float s[32][33];
    const int wsel = blockIdx.z;
    const float* W = (wsel == 0) ? w0 : (wsel == 1) ? w1 : (wsel == 2) ? w2 : w3;
    const float scale = (wsel == 0) ? 0.125f * 1.44269504f : 1.0f;
    const int k0 = blockIdx.x * 32, n0 = blockIdx.y * 32;
    const int tx = threadIdx.x, ty = threadIdx.y;
    #pragma unroll
    for (int i = 0; i < 4; i++)
        s[ty + 8 * i][tx] = W[(size_t)(k0 + ty + 8 * i) * DMODEL + n0 + tx];
    __syncthreads();
    const size_t base = (size_t)wsel * WSZ;
    #pragma unroll
    for (int i = 0; i < 4; i++) {
        int n = n0 + ty + 8 * i, k = k0 + tx;
        g_W16[base + (size_t)n * DMODEL + k] = __float2half_rn(s[tx][ty + 8 * i] * scale);
    }
}

// ---- QKV GEMM: fp16, BK=64, 2-stage; A loaded fp32 directly ----------------------
#define STGB 32768
__global__ __launch_bounds__(256)
void gemm_qkv(const float* __restrict__ x0, const float* __restrict__ x1,
              const float* __restrict__ x2)
{
    extern __shared__ char dyn[];
    const uint32_t sbu = smem_u32(dyn);
    const int tid = threadIdx.x, wid = tid >> 5, lane = tid & 31;
    const int wm = wid & 1, wn = wid >> 1;
    const int g8 = lane >> 3, r8 = lane & 7;
    const int bx = blockIdx.x, by = blockIdx.y;
    const int wsel = blockIdx.z;
    const float* X = (wsel == 0) ? x0 : (wsel == 1) ? x1 : x2;
    const __half* Bp = g_W16 + (size_t)wsel * WSZ;
    const int arow = by * 128, brow = bx * 128;

    float4 areg[4][2];
    auto ldgA = [&](int k0) {
        #pragma unroll
        for (int i = 0; i < 4; i++) {
            int idx = tid + i * 256;
            int r = idx >> 3, ch = idx & 7;
            const float* src = X + (size_t)(arow + r) * DMODEL + k0 + ch * 8;
            areg[i][0] = *(const float4*)src;
            areg[i][1] = *(const float4*)(src + 4);
        }
    };
    auto stsA = [&](int s) {
        #pragma unroll
        for (int i = 0; i < 4; i++) {
            int idx = tid + i * 256;
            int r = idx >> 3, ch = idx & 7;
            uint4 p;
            p.x = packhf(areg[i][0].x, areg[i][0].y);
            p.y = packhf(areg[i][0].z, areg[i][0].w);
            p.z = packhf(areg[i][1].x, areg[i][1].y);
            p.w = packhf(areg[i][1].z, areg[i][1].w);
            *(uint4*)(dyn + s * STGB + r * 128 + ((ch ^ (r & 7)) << 4)) = p;
        }
    };
    auto cpaB = [&](int s, int k0) {
        uint32_t base = sbu + (uint32_t)s * STGB + 16384u;
        #pragma unroll
        for (int i = 0; i < 4; i++) {
            int idx = tid + i * 256;
            int r = idx >> 3, ch = idx & 7;
            cpa16(base + (uint32_t)r * 128u + (uint32_t)((ch ^ (r & 7)) << 4),
                  Bp + (size_t)(brow + r) * DMODEL + k0 + ch * 8);
        }
    };

    float d[4][4][4];
    #pragma unroll
    for (int mi = 0; mi < 4; mi++)
        #pragma unroll
        for (int ni = 0; ni < 4; ni++)
            #pragma unroll
            for (int q = 0; q < 4; q++) d[mi][ni][q] = 0.0f;

    ldgA(0); stsA(0); cpaB(0, 0); CP_COMMIT();

    for (int c = 0; c < 8; c++) {
        if (c < 7) {
            ldgA((c + 1) * 64);
            cpaB((c + 1) & 1, (c + 1) * 64);
            CP_COMMIT(); CP_WAIT(1);
        } else { CP_WAIT(0); }
        __syncthreads();

        const uint32_t ss = sbu + (uint32_t)(c & 1) * STGB;
        #pragma unroll
        for (int k16 = 0; k16 < 4; k16++) {
            uint32_t ah[4][4], bh[8];
            #pragma unroll
            for (int mi = 0; mi < 4; mi++) {
                int row = wm * 64 + mi * 16 + r8 + (g8 & 1) * 8;
                int ch  = k16 * 2 + (g8 >> 1);
                ldmx4(ss + (uint32_t)row * 128u + (uint32_t)((ch ^ (row & 7)) << 4), ah[mi]);
            }
            #pragma unroll
            for (int np = 0; np < 2; np++) {
                int row = wn * 32 + np * 16 + r8 + (g8 >> 1) * 8;
                int ch  = k16 * 2 + (g8 & 1);
                ldmx4(ss + 16384u + (uint32_t)row * 128u
                         + (uint32_t)((ch ^ (row & 7)) << 4), &bh[np * 4]);
            }
            #pragma unroll
            for (int mi = 0; mi < 4; mi++)
                #pragma unroll
                for (int ni = 0; ni < 4; ni++)
                    mma16816(d[mi][ni], ah[mi], &bh[ni * 2]);
        }
        if (c < 7) stsA((c + 1) & 1);
        __syncthreads();
    }

    __half* dst = (wsel == 0) ? g_Q16 : (wsel == 1) ? g_K16 : g_V16;
    const int rbase = by * 128 + wm * 64 + (lane >> 2);
    const int cbase = bx * 128 + wn * 32 + (lane & 3) * 2;
    #pragma unroll
    for (int mi = 0; mi < 4; mi++)
        #pragma unroll
        for (int ni = 0; ni < 4; ni++) {
            int col = cbase + ni * 8;
            #pragma unroll
            for (int hf = 0; hf < 2; hf++) {
                int row = rbase + mi * 16 + hf * 8;
                *(uint32_t*)(dst + (size_t)row * DMODEL + col) =
                    packhf(d[mi][ni][hf * 2], d[mi][ni][hf * 2 + 1]);
            }
        }
}

// ---- fused out-proj + residual + LayerNorm: 512 threads (16 warps, 4/SMSP) --------
// CTA tile: 64 rows x 512 cols; warp wid owns cols [wid*32, wid*32+32).
// stage s (73728B): A 64x128B @ s*73728, B 512x128B @ +8192. 2 stages.
// red @147456 (4KB), redq @151552 (4KB), stats @155648 (512B). total 156160.
#define GLSTG 73728
#define GL_SMEM 156160
__global__ __launch_bounds__(512)
void gemm_ln(const float* __restrict__ resid, float* __restrict__ out)
{
    extern __shared__ char dyn[];
    const uint32_t sb = smem_u32(dyn);
    float* red   = (float*)(dyn + 147456);
    float* redq  = (float*)(dyn + 151552);
    float* stats = (float*)(dyn + 155648);

    const int tid = threadIdx.x, wid = tid >> 5, lane = tid & 31;
    const int g8 = lane >> 3, r8 = lane & 7;
    const int m0 = blockIdx.x * 64;
    const __half* A = g_C16;
    const __half* B = g_W16 + 3 * WSZ;

    auto stage = [&](int s, int k0) {
        uint32_t sA = sb + (uint32_t)s * GLSTG;
        uint32_t sB = sA + 8192u;
        {
            int r = tid >> 3, c = tid & 7;   // 512 threads = 64 rows x 8 chunks
            cpa16(sA + (uint32_t)r * 128u + (uint32_t)((c ^ (r & 7)) << 4),
                  A + (size_t)(m0 + r) * DMODEL + k0 + c * 8);
        }
        #pragma unroll
        for (int i = 0; i < 8; i++) {
            int idx = tid + i * 512;
            int r = idx >> 3, c = idx & 7;
            cpa16(sB + (uint32_t)r * 128u + (uint32_t)((c ^ (r & 7)) << 4),
                  B + (size_t)r * DMODEL + k0 + c * 8);
        }
    };

    float d[4][4][4];
    #pragma unroll
    for (int mi = 0; mi < 4; mi++)
        #pragma unroll
        for (int ni = 0; ni < 4; ni++)
            #pragma unroll
            for (int q = 0; q < 4; q++) d[mi][ni][q] = 0.0f;

    stage(0, 0); CP_COMMIT();

    for (int c = 0; c < 8; c++) {
        if (c < 7) {
            stage((c + 1) & 1, (c + 1) * 64);
            CP_COMMIT(); CP_WAIT(1);
        } else { CP_WAIT(0); }
        __syncthreads();

        const uint32_t sA = sb + (uint32_t)(c & 1) * GLSTG;
        const uint32_t sB = sA + 8192u;
        #pragma unroll
        for (int k16 = 0; k16 < 4; k16++) {
            uint32_t ah[4][4], bh[8];
            #pragma unroll
            for (int mi = 0; mi < 4; mi++) {
                int row = mi * 16 + r8 + (g8 & 1) * 8;
                int ch  = k16 * 2 + (g8 >> 1);
                ldmx4(sA + (uint32_t)row * 128u + (uint32_t)((ch ^ (row & 7)) << 4), ah[mi]);
            }
            #pragma unroll
            for (int np = 0; np < 2; np++) {
                int row = wid * 32 + np * 16 + r8 + (g8 >> 1) * 8;
                int ch  = k16 * 2 + (g8 & 1);
                ldmx4(sB + (uint32_t)row * 128u + (uint32_t)((ch ^ (row & 7)) << 4),
                      &bh[np * 4]);
            }
            #pragma unroll
            for (int mi = 0; mi < 4; mi++)
                #pragma unroll
                for (int ni = 0; ni < 4; ni++)
                    mma16816(d[mi][ni], ah[mi], &bh[ni * 2]);
        }
        __syncthreads();
    }

    // epilogue: residual + per-row partial moments (warp strip = 32 cols)
    const int lrow0 = lane >> 2;
    #pragma unroll
    for (int mi = 0; mi < 4; mi++)
        #pragma unroll
        for (int hf = 0; hf < 2; hf++) {
            int lrow = mi * 16 + hf * 8 + lrow0;
            int grow = m0 + lrow;
            float s = 0.0f, sq = 0.0f;
            #pragma unroll
            for (int ni = 0; ni < 4; ni++) {
                int col = wid * 32 + ni * 8 + (lane & 3) * 2;
                float2 rv = *(const float2*)(resid + (size_t)grow * DMODEL + col);
                float v0 = d[mi][ni][hf * 2]     + rv.x;
                float v1 = d[mi][ni][hf * 2 + 1] + rv.y;
                d[mi][ni][hf * 2]     = v0;
                d[mi][ni][hf * 2 + 1] = v1;
                s  += v0 + v1;
                sq += v0 * v0 + v1 * v1;
            }
            s  += __shfl_xor_sync(0xffffffffu, s, 1);
            s  += __shfl_xor_sync(0xffffffffu, s, 2);
            sq += __shfl_xor_sync(0xffffffffu, sq, 1);
            sq += __shfl_xor_sync(0xffffffffu, sq, 2);
            if ((lane & 3) == 0) {
                red [lrow * 16 + wid] = s;
                redq[lrow * 16 + wid] = sq;
            }
        }
    __syncthreads();

    if (tid < 64) {
        float s = 0.0f, sq = 0.0f;
        #pragma unroll
        for (int w = 0; w < 16; w++) { s += red[tid * 16 + w]; sq += redq[tid * 16 + w]; }
        float mean = s * (1.0f / DMODEL);
        float var  = sq * (1.0f / DMODEL) - mean * mean;
        stats[tid * 2]     = mean;
        stats[tid * 2 + 1] = rsqrtf(var + 1e-5f);
    }
    __syncthreads();

    #pragma unroll
    for (int mi = 0; mi < 4; mi++)
        #pragma unroll
        for (int hf = 0; hf < 2; hf++) {
            int lrow = mi * 16 + hf * 8 + lrow0;
            float mean = stats[lrow * 2], rstd = stats[lrow * 2 + 1];
            int grow = m0 + lrow;
            #pragma unroll
            for (int ni = 0; ni < 4; ni++) {
                int col = wid * 32 + ni * 8 + (lane & 3) * 2;
                float v0 = (d[mi][ni][hf * 2]     - mean) * rstd;
                float v1 = (d[mi][ni][hf * 2 + 1] - mean) * rstd;
                *(float2*)(out + (size_t)grow * DMODEL + col) = make_float2(v0, v1);
            }
        }
}

// ---- attention: fp16 flash, banded, fixed-base softmax (MUFU.EX2) ------------------
__device__ __forceinline__ void stage_kv(uint32_t sb, int s, int b, int h,
                                         int krow0, int tid)
{
    const uint32_t base = sb + 8192u + (uint32_t)s * 16384u;
    #pragma unroll
    for (int i = 0; i < 8; i++) {
        int idx = tid + i * 128;
        int mat = idx >> 9, rem = idx & 511;
        int r = rem >> 3, ch = rem & 7;
        const __half* src = (mat ? g_V16 : g_K16)
            + (size_t)(b * SEQL + krow0 + r) * DMODEL + h * HDIM + ch * 8;
        cpa16(base + (uint32_t)mat * 8192u + (uint32_t)r * 128u
                   + (uint32_t)((ch ^ (r & 7)) << 4), src);
    }
}

__global__ __launch_bounds__(128, 3)
void attn_tc()
{
    extern __shared__ char dyn[];
    const uint32_t sb = smem_u32(dyn);
    const int tid = threadIdx.x, wid = tid >> 5, lane = tid & 31;
    const int r8 = lane & 7, g8 = lane >> 3;
    const int qt = blockIdx.x, h = blockIdx.y, b = blockIdx.z;
    const int q0 = qt * 64;

    #pragma unroll
    for (int i = 0; i < 4; i++) {
        int idx = tid + i * 128;
        int r = idx >> 3, ch = idx & 7;
        const __half* src = g_Q16
            + (size_t)(b * SEQL + q0 + r) * DMODEL + h * HDIM + ch * 8;
        cpa16(sb + (uint32_t)r * 128u + (uint32_t)((ch ^ (r & 7)) << 4), src);
    }
    const int kt_lo = (qt >= 4) ? qt - 4 : 0;
    stage_kv(sb, 0, b, h, kt_lo * 64, tid);
    CP_COMMIT(); CP_WAIT(0);
    __syncthreads();

    uint32_t qh[4][4];
    #pragma unroll
    for (int k16 = 0; k16 < 4; k16++) {
        int row = wid * 16 + r8 + (g8 & 1) * 8;
        int ch  = k16 * 2 + (g8 >> 1);
        ldmx4(sb + (uint32_t)row * 128u + (uint32_t)((ch ^ (row & 7)) << 4), qh[k16]);
    }

    float o[8][4];
    #pragma unroll
    for (int ni = 0; ni < 8; ni++)
        #pragma unroll
        for (int c = 0; c < 4; c++) o[ni][c] = 0.0f;
    float l0 = 0.0f, l1 = 0.0f;

    for (int kt = kt_lo; kt <= qt; kt++) {
        const int s = (kt - kt_lo) & 1;
        if (kt < qt) { stage_kv(sb, s ^ 1, b, h, (kt + 1) * 64, tid); CP_COMMIT(); }
        const uint32_t kb = sb + 8192u + (uint32_t)s * 16384u;

        float sc[8][4];
        #pragma unroll
        for (int ni = 0; ni < 8; ni++)
            #pragma unroll
            for (int c = 0; c < 4; c++) sc[ni][c] = 0.0f;

        #pragma unroll
        for (int k16 = 0; k16 < 4; k16++) {
            uint32_t kh[4][4];
            #pragma unroll
            for (int ng = 0; ng < 4; ng++) {
                int row = ng * 16 + r8 + (g8 >> 1) * 8;
                int ch  = k16 * 2 + (g8 & 1);
                ldmx4(kb + (uint32_t)row * 128u + (uint32_t)((ch ^ (row & 7)) << 4), kh[ng]);
            }
            #pragma unroll
            for (int ng = 0; ng < 4; ng++)
                #pragma unroll
                for (int hf = 0; hf < 2; hf++)
                    mma16816(sc[ng * 2 + hf], qh[k16], &kh[ng][hf * 2]);
        }

        const int k0 = kt * 64;
        if (kt == qt || (qt >= 4 && kt == qt - 4)) {
            const bool diag = (kt == qt);
            const int qr0 = q0 + wid * 16 + (lane >> 2);
            #pragma unroll
            for (int ni = 0; ni < 8; ni++) {
                int kj = k0 + ni * 8 + 2 * (lane & 3);
                #pragma unroll
                for (int c = 0; c < 4; c++) {
                    int kcol = kj + (c & 1), qrow = qr0 + (c >> 1) * 8;
                    bool ok = diag ? (kcol <= qrow) : (kcol >= qrow - (WINDOW - 1));
                    if (!ok) sc[ni][c] = -INFINITY;
                }
            }
        }

        #pragma unroll
        for (int ni = 0; ni < 8; ni++) {
            sc[ni][0] = ex2(sc[ni][0]);
            sc[ni][1] = ex2(sc[ni][1]);
            sc[ni][2] = ex2(sc[ni][2]);
            sc[ni][3] = ex2(sc[ni][3]);
            l0 += sc[ni][0] + sc[ni][1];
            l1 += sc[ni][2] + sc[ni][3];
        }

        uint32_t ph[4][4];
        #pragma unroll
        for (int t = 0; t < 4; t++) {
            ph[t][0] = packhf(sc[2*t][0],   sc[2*t][1]);
            ph[t][1] = packhf(sc[2*t][2],   sc[2*t][3]);
            ph[t][2] = packhf(sc[2*t+1][0], sc[2*t+1][1]);
            ph[t][3] = packhf(sc[2*t+1][2], sc[2*t+1][3]);
        }

        const uint32_t vb = kb + 8192u;
        #pragma unroll
        for (int kt16 = 0; kt16 < 4; kt16++) {
            uint32_t vh[4][4];
            #pragma unroll
            for (int ng = 0; ng < 4; ng++) {
                int row = kt16 * 16 + r8 + (g8 & 1) * 8;
                int ch  = ng * 2 + (g8 >> 1);
                ldmx4t(vb + (uint32_t)row * 128u + (uint32_t)((ch ^ (row & 7)) << 4), vh[ng]);
            }
            #pragma unroll
            for (int ng = 0; ng < 4; ng++)
                #pragma unroll
                for (int hf = 0; hf < 2; hf++)
                    mma16816(o[ng * 2 + hf], ph[kt16], &vh[ng][hf * 2]);
        }
        if (kt < qt) { CP_WAIT(0); __syncthreads(); }
    }

    l0 += __shfl_xor_sync(0xffffffffu, l0, 1);
    l0 += __shfl_xor_sync(0xffffffffu, l0, 2);
    l1 += __shfl_xor_sync(0xffffffffu, l1, 1);
    l1 += __shfl_xor_sync(0xffffffffu, l1, 2);

    const float i0 = 1.0f / l0, i1 = 1.0f / l1;
    const int row0 = q0 + wid * 16 + (lane >> 2);
    #pragma unroll
    for (int ni = 0; ni < 8; ni++) {
        int col = h * HDIM + ni * 8 + 2 * (lane & 3);
        size_t o0 = (size_t)(b * SEQL + row0) * DMODEL + col;
        *(uint32_t*)(g_C16 + o0) = packhf(o[ni][0] * i0, o[ni][1] * i0);
        *(uint32_t*)(g_C16 + o0 + 8 * DMODEL) = packhf(o[ni][2] * i1, o[ni][3] * i1);
    }
}

// ---------------------------------------------------------------------------------------
extern "C" void kernel_launch(void* const* d_in, const int* in_sizes, int n_in,
                              void* d_out, int out_size)
{
    const float* iQ = (const float*)d_in[0];
    const float* iK = (const float*)d_in[1];
    const float* iV = (const float*)d_in[2];
    const float* wQ = (const float*)d_in[3];
    const float* wK = (const float*)d_in[4];
    const float* wV = (const float*)d_in[5];
    const float* wF = (const float*)d_in[6];
    float* out = (float*)d_out;

    prep_w_kernel<<<dim3(16, 16, 4), dim3(32, 8)>>>(wQ, wK, wV, wF);

    const int gemm_smem = 2 * STGB;   // 65536
    cudaFuncSetAttribute((const void*)gemm_qkv,
                         cudaFuncAttributeMaxDynamicSharedMemorySize, gemm_smem);
    cudaFuncSetAttribute((const void*)gemm_ln,
                         cudaFuncAttributeMaxDynamicSharedMemorySize, GL_SMEM);
    cudaFuncSetAttribute((const void*)attn_tc,
                         cudaFuncAttributeMaxDynamicSharedMemorySize, 40960);

    gemm_qkv<<<dim3(4, 64, 3), 256, gemm_smem>>>(iQ, iK, iV);
    attn_tc<<<dim3(SEQL / 64, NHEAD, NB), 128, 40960>>>();
    gemm_ln<<<MTOT / 64, 512, GL_SMEM>>>(iQ, out);
}

// round 14
// speedup vs baseline: 1.0945x; 1.0087x over previous
#include <cuda_runtime.h>
#include <cuda_fp16.h>
#include <math.h>
#include <stdint.h>

#define NB 4
#define SEQL 2048
#define DMODEL 512
#define NHEAD 8
#define HDIM 64
#define WINDOW 256
#define MTOT (NB*SEQL)
#define XSZ ((size_t)MTOT*DMODEL)
#define WSZ ((size_t)DMODEL*DMODEL)

__device__ __align__(16) __half g_W16[4*DMODEL*DMODEL];   // W^T fp16, [w][n][k]
__device__ __align__(16) __half g_Q16[MTOT*DMODEL];       // Q has 0.125*log2e folded
__device__ __align__(16) __half g_K16[MTOT*DMODEL];
__device__ __align__(16) __half g_V16[MTOT*DMODEL];
__device__ __align__(16) __half g_C16[MTOT*DMODEL];       // ctx fp16

__device__ __forceinline__ uint32_t smem_u32(const void* p) {
    uint32_t a;
    asm("{ .reg .u64 t; cvta.to.shared.u64 t, %1; cvt.u32.u64 %0, t; }" : "=r"(a) : "l"(p));
    return a;
}
__device__ __forceinline__ void cpa16(uint32_t dst, const void* src) {
    asm volatile("cp.async.cg.shared.global [%0], [%1], 16;" :: "r"(dst), "l"(src));
}
#define CP_COMMIT() asm volatile("cp.async.commit_group;")
#define CP_WAIT(n)  asm volatile("cp.async.wait_group " #n ";")
__device__ __forceinline__ void ldmx4(uint32_t a, uint32_t* r) {
    asm volatile("ldmatrix.sync.aligned.m8n8.x4.shared.b16 {%0,%1,%2,%3}, [%4];"
                 : "=r"(r[0]), "=r"(r[1]), "=r"(r[2]), "=r"(r[3]) : "r"(a));
}
__device__ __forceinline__ void ldmx4t(uint32_t a, uint32_t* r) {
    asm volatile("ldmatrix.sync.aligned.m8n8.x4.trans.shared.b16 {%0,%1,%2,%3}, [%4];"
                 : "=r"(r[0]), "=r"(r[1]), "=r"(r[2]), "=r"(r[3]) : "r"(a));
}
__device__ __forceinline__ void mma16816(float* d, const uint32_t* a, const uint32_t* b) {
    asm volatile("mma.sync.aligned.m16n8k16.row.col.f32.f16.f16.f32 "
                 "{%0,%1,%2,%3}, {%4,%5,%6,%7}, {%8,%9}, {%0,%1,%2,%3};"
                 : "+f"(d[0]), "+f"(d[1]), "+f"(d[2]), "+f"(d[3])
                 : "r"(a[0]), "r"(a[1]), "r"(a[2]), "r"(a[3]), "r"(b[0]), "r"(b[1]));
}
__device__ __forceinline__ uint32_t packhf(float v0, float v1) {
    __half2 h = __floats2half2_rn(v0, v1);
    return *(uint32_t*)&h;
}
__device__ __forceinline__ float ex2(float x) {
    asm("ex2.approx.f32 %0, %0;" : "+f"(x));
    return x;
}
__device__ __forceinline__ uint32_t mapa_peer(uint32_t addr, uint32_t rank) {
    uint32_t r;
    asm("mapa.shared::cluster.u32 %0, %1, %2;" : "=r"(r) : "r"(addr), "r"(rank));
    return r;
}
__device__ __forceinline__ float ld_dsm(uint32_t addr) {
    float v;
    asm volatile("ld.shared::cluster.f32 %0, [%1];" : "=f"(v) : "r"(addr));
    return v;
}
#define CLUSTER_SYNC() do { \
    asm volatile("barrier.cluster.arrive.aligned;" ::: "memory"); \
    asm volatile("barrier.cluster.wait.aligned;" ::: "memory"); \
} while (0)

// ---- prep: W^T fp16 (0.125*log2e folded into W_Q) ------------------------------
__global__ __launch_bounds__(256)
void prep_w_kernel(const float* __restrict__ w0, const float* __restrict__ w1,
                   const float* __restrict__ w2, const float* __restrict__ w3)
{
    __shared__ float s[32][33];
    const int wsel = blockIdx.z;
    const float* W = (wsel == 0) ? w0 : (wsel == 1) ? w1 : (wsel == 2) ? w2 : w3;
    const float scale = (wsel == 0) ? 0.125f * 1.44269504f : 1.0f;
    const int k0 = blockIdx.x * 32, n0 = blockIdx.y * 32;
    const int tx = threadIdx.x, ty = threadIdx.y;
    #pragma unroll
    for (int i = 0; i < 4; i++)
        s[ty + 8 * i][tx] = W[(size_t)(k0 + ty + 8 * i) * DMODEL + n0 + tx];
    __syncthreads();
    const size_t base = (size_t)wsel * WSZ;
    #pragma unroll
    for (int i = 0; i < 4; i++) {
        int n = n0 + ty + 8 * i, k = k0 + tx;
        g_W16[base + (size_t)n * DMODEL + k] = __float2half_rn(s[tx][ty + 8 * i] * scale);
    }
}

// ---- QKV GEMM: fp16, BK=64, 2-stage; A loaded fp32 directly (unchanged) ----------
#define STGB 32768
__global__ __launch_bounds__(256)
void gemm_qkv(const float* __restrict__ x0, const float* __restrict__ x1,
              const float* __restrict__ x2)
{
    extern __shared__ char dyn[];
    const uint32_t sbu = smem_u32(dyn);
    const int tid = threadIdx.x, wid = tid >> 5, lane = tid & 31;
    const int wm = wid & 1, wn = wid >> 1;
    const int g8 = lane >> 3, r8 = lane & 7;
    const int bx = blockIdx.x, by = blockIdx.y;
    const int wsel = blockIdx.z;
    const float* X = (wsel == 0) ? x0 : (wsel == 1) ? x1 : x2;
    const __half* Bp = g_W16 + (size_t)wsel * WSZ;
    const int arow = by * 128, brow = bx * 128;

    float4 areg[4][2];
    auto ldgA = [&](int k0) {
        #pragma unroll
        for (int i = 0; i < 4; i++) {
            int idx = tid + i * 256;
            int r = idx >> 3, ch = idx & 7;
            const float* src = X + (size_t)(arow + r) * DMODEL + k0 + ch * 8;
            areg[i][0] = *(const float4*)src;
            areg[i][1] = *(const float4*)(src + 4);
        }
    };
    auto stsA = [&](int s) {
        #pragma unroll
        for (int i = 0; i < 4; i++) {
            int idx = tid + i * 256;
            int r = idx >> 3, ch = idx & 7;
            uint4 p;
            p.x = packhf(areg[i][0].x, areg[i][0].y);
            p.y = packhf(areg[i][0].z, areg[i][0].w);
            p.z = packhf(areg[i][1].x, areg[i][1].y);
            p.w = packhf(areg[i][1].z, areg[i][1].w);
            *(uint4*)(dyn + s * STGB + r * 128 + ((ch ^ (r & 7)) << 4)) = p;
        }
    };
    auto cpaB = [&](int s, int k0) {
        uint32_t base = sbu + (uint32_t)s * STGB + 16384u;
        #pragma unroll
        for (int i = 0; i < 4; i++) {
            int idx = tid + i * 256;
            int r = idx >> 3, ch = idx & 7;
            cpa16(base + (uint32_t)r * 128u + (uint32_t)((ch ^ (r & 7)) << 4),
                  Bp + (size_t)(brow + r) * DMODEL + k0 + ch * 8);
        }
    };

    float d[4][4][4];
    #pragma unroll
    for (int mi = 0; mi < 4; mi++)
        #pragma unroll
        for (int ni = 0; ni < 4; ni++)
            #pragma unroll
            for (int q = 0; q < 4; q++) d[mi][ni][q] = 0.0f;

    ldgA(0); stsA(0); cpaB(0, 0); CP_COMMIT();

    for (int c = 0; c < 8; c++) {
        if (c < 7) {
            ldgA((c + 1) * 64);
            cpaB((c + 1) & 1, (c + 1) * 64);
            CP_COMMIT(); CP_WAIT(1);
        } else { CP_WAIT(0); }
        __syncthreads();

        const uint32_t ss = sbu + (uint32_t)(c & 1) * STGB;
        #pragma unroll
        for (int k16 = 0; k16 < 4; k16++) {
            uint32_t ah[4][4], bh[8];
            #pragma unroll
            for (int mi = 0; mi < 4; mi++) {
                int row = wm * 64 + mi * 16 + r8 + (g8 & 1) * 8;
                int ch  = k16 * 2 + (g8 >> 1);
                ldmx4(ss + (uint32_t)row * 128u + (uint32_t)((ch ^ (row & 7)) << 4), ah[mi]);
            }
            #pragma unroll
            for (int np = 0; np < 2; np++) {
                int row = wn * 32 + np * 16 + r8 + (g8 >> 1) * 8;
                int ch  = k16 * 2 + (g8 & 1);
                ldmx4(ss + 16384u + (uint32_t)row * 128u
                         + (uint32_t)((ch ^ (row & 7)) << 4), &bh[np * 4]);
            }
            #pragma unroll
            for (int mi = 0; mi < 4; mi++)
                #pragma unroll
                for (int ni = 0; ni < 4; ni++)
                    mma16816(d[mi][ni], ah[mi], &bh[ni * 2]);
        }
        if (c < 7) stsA((c + 1) & 1);
        __syncthreads();
    }

    __half* dst = (wsel == 0) ? g_Q16 : (wsel == 1) ? g_K16 : g_V16;
    const int rbase = by * 128 + wm * 64 + (lane >> 2);
    const int cbase = bx * 128 + wn * 32 + (lane & 3) * 2;
    #pragma unroll
    for (int mi = 0; mi < 4; mi++)
        #pragma unroll
        for (int ni = 0; ni < 4; ni++) {
            int col = cbase + ni * 8;
            #pragma unroll
            for (int hf = 0; hf < 2; hf++) {
                int row = rbase + mi * 16 + hf * 8;
                *(uint32_t*)(dst + (size_t)row * DMODEL + col) =
                    packhf(d[mi][ni][hf * 2], d[mi][ni][hf * 2 + 1]);
            }
        }
}

// ---- cluster-fused out-proj + residual + LayerNorm --------------------------------
// cluster (2,1,1): CTA bx owns cols [bx*256, bx*256+256), by owns rows [by*64,+64).
// 256 threads, warp wm=wid&1 (32 rows), wn=wid>>1 (64 cols). 2 CTAs/SM (80KB smem).
// smem: stage s @ s*40960 (A 8KB @0, B 32KB @8192); red @81920 (1KB), redq @82944,
//       partial @83968 (512B: s,sq per row), stats @84480 (512B). total 84992.
#define CLSTG 40960
#define CL_SMEM 84992
__global__ __launch_bounds__(256) __cluster_dims__(2, 1, 1)
void gemm_ln(const float* __restrict__ resid, float* __restrict__ out)
{
    extern __shared__ char dyn[];
    const uint32_t sb = smem_u32(dyn);
    float* red     = (float*)(dyn + 81920);
    float* redq    = (float*)(dyn + 82944);
    float* partial = (float*)(dyn + 83968);
    float* stats   = (float*)(dyn + 84480);

    const int tid = threadIdx.x, wid = tid >> 5, lane = tid & 31;
    const int wm = wid & 1, wn = wid >> 1;
    const int g8 = lane >> 3, r8 = lane & 7;
    const uint32_t bx = blockIdx.x;          // == cluster ctarank (cluster dims 2,1,1)
    const int m0 = blockIdx.y * 64;
    const int c0 = bx * 256;
    const __half* A = g_C16;
    const __half* B = g_W16 + 3 * WSZ + (size_t)c0 * DMODEL;

    auto stage = [&](int s, int k0) {
        uint32_t sA = sb + (uint32_t)s * CLSTG;
        uint32_t sB = sA + 8192u;
        #pragma unroll
        for (int i = 0; i < 2; i++) {                       // A: 64 rows
            int idx = tid + i * 256;
            int r = idx >> 3, c = idx & 7;
            cpa16(sA + (uint32_t)r * 128u + (uint32_t)((c ^ (r & 7)) << 4),
                  A + (size_t)(m0 + r) * DMODEL + k0 + c * 8);
        }
        #pragma unroll
        for (int i = 0; i < 8; i++) {                       // B: 256 rows
            int idx = tid + i * 256;
            int r = idx >> 3, c = idx & 7;
            cpa16(sB + (uint32_t)r * 128u + (uint32_t)((c ^ (r & 7)) << 4),
                  B + (size_t)r * DMODEL + k0 + c * 8);
        }
    };

    float d[2][8][4];
    #pragma unroll
    for (int mi = 0; mi < 2; mi++)
        #pragma unroll
        for (int ni = 0; ni < 8; ni++)
            #pragma unroll
            for (int q = 0; q < 4; q++) d[mi][ni][q] = 0.0f;

    stage(0, 0); CP_COMMIT();

    for (int c = 0; c < 8; c++) {
        if (c < 7) {
            stage((c + 1) & 1, (c + 1) * 64);
            CP_COMMIT(); CP_WAIT(1);
        } else { CP_WAIT(0); }
        __syncthreads();

        const uint32_t sA = sb + (uint32_t)(c & 1) * CLSTG;
        const uint32_t sB = sA + 8192u;
        #pragma unroll
        for (int k16 = 0; k16 < 4; k16++) {
            uint32_t ah[2][4], bh[16];
            #pragma unroll
            for (int mi = 0; mi < 2; mi++) {
                int row = wm * 32 + mi * 16 + r8 + (g8 & 1) * 8;
                int ch  = k16 * 2 + (g8 >> 1);
                ldmx4(sA + (uint32_t)row * 128u + (uint32_t)((ch ^ (row & 7)) << 4), ah[mi]);
            }
            #pragma unroll
            for (int np = 0; np < 4; np++) {
                int row = wn * 64 + np * 16 + r8 + (g8 >> 1) * 8;
                int ch  = k16 * 2 + (g8 & 1);
                ldmx4(sB + (uint32_t)row * 128u + (uint32_t)((ch ^ (row & 7)) << 4),
                      &bh[np * 4]);
            }
            #pragma unroll
            for (int mi = 0; mi < 2; mi++)
                #pragma unroll
                for (int ni = 0; ni < 8; ni++)
                    mma16816(d[mi][ni], ah[mi], &bh[(ni >> 1) * 4 + (ni & 1) * 2]);
        }
        __syncthreads();
    }

    // epilogue: residual + per-row partial moments over this CTA's 256 cols
    const int lrow0 = lane >> 2;
    #pragma unroll
    for (int mi = 0; mi < 2; mi++)
        #pragma unroll
        for (int hf = 0; hf < 2; hf++) {
            int lrow = wm * 32 + mi * 16 + hf * 8 + lrow0;
            int grow = m0 + lrow;
            float s = 0.0f, sq = 0.0f;
            #pragma unroll
            for (int ni = 0; ni < 8; ni++) {
                int col = c0 + wn * 64 + ni * 8 + (lane & 3) * 2;
                float2 rv = *(const float2*)(resid + (size_t)grow * DMODEL + col);
                float v0 = d[mi][ni][hf * 2]     + rv.x;
                float v1 = d[mi][ni][hf * 2 + 1] + rv.y;
                d[mi][ni][hf * 2]     = v0;
                d[mi][ni][hf * 2 + 1] = v1;
                s  += v0 + v1;
                sq += v0 * v0 + v1 * v1;
            }
            s  += __shfl_xor_sync(0xffffffffu, s, 1);
            s  += __shfl_xor_sync(0xffffffffu, s, 2);
            sq += __shfl_xor_sync(0xffffffffu, sq, 1);
            sq += __shfl_xor_sync(0xffffffffu, sq, 2);
            if ((lane & 3) == 0) {
                red [lrow * 4 + wn] = s;
                redq[lrow * 4 + wn] = sq;
            }
        }
    __syncthreads();

    if (tid < 64) {
        float s = 0.0f, sq = 0.0f;
        #pragma unroll
        for (int w = 0; w < 4; w++) { s += red[tid * 4 + w]; sq += redq[tid * 4 + w]; }
        partial[tid * 2]     = s;
        partial[tid * 2 + 1] = sq;
    }
    CLUSTER_SYNC();   // publish partials cluster-wide

    if (tid < 64) {
        uint32_t paddr = mapa_peer(sb + 83968u + (uint32_t)tid * 8u, bx ^ 1u);
        float s  = partial[tid * 2]     + ld_dsm(paddr);
        float sq = partial[tid * 2 + 1] + ld_dsm(paddr + 4u);
        float mean = s * (1.0f / DMODEL);
        float var  = sq * (1.0f / DMODEL) - mean * mean;
        stats[tid * 2]     = mean;
        stats[tid * 2 + 1] = rsqrtf(var + 1e-5f);
    }
    __syncthreads();

    #pragma unroll
    for (int mi = 0; mi < 2; mi++)
        #pragma unroll
        for (int hf = 0; hf < 2; hf++) {
            int lrow = wm * 32 + mi * 16 + hf * 8 + lrow0;
            float mean = stats[lrow * 2], rstd = stats[lrow * 2 + 1];
            int grow = m0 + lrow;
            #pragma unroll
            for (int ni = 0; ni < 8; ni++) {
                int col = c0 + wn * 64 + ni * 8 + (lane & 3) * 2;
                float v0 = (d[mi][ni][hf * 2]     - mean) * rstd;
                float v1 = (d[mi][ni][hf * 2 + 1] - mean) * rstd;
                *(float2*)(out + (size_t)grow * DMODEL + col) = make_float2(v0, v1);
            }
        }
}

// ---- attention: fp16 flash, banded, fixed-base softmax (unchanged) -----------------
__device__ __forceinline__ void stage_kv(uint32_t sb, int s, int b, int h,
                                         int krow0, int tid)
{
    const uint32_t base = sb + 8192u + (uint32_t)s * 16384u;
    #pragma unroll
    for (int i = 0; i < 8; i++) {
        int idx = tid + i * 128;
        int mat = idx >> 9, rem = idx & 511;
        int r = rem >> 3, ch = rem & 7;
        const __half* src = (mat ? g_V16 : g_K16)
            + (size_t)(b * SEQL + krow0 + r) * DMODEL + h * HDIM + ch * 8;
        cpa16(base + (uint32_t)mat * 8192u + (uint32_t)r * 128u
                   + (uint32_t)((ch ^ (r & 7)) << 4), src);
    }
}

__global__ __launch_bounds__(128, 3)
void attn_tc()
{
    extern __shared__ char dyn[];
    const uint32_t sb = smem_u32(dyn);
    const int tid = threadIdx.x, wid = tid >> 5, lane = tid & 31;
    const int r8 = lane & 7, g8 = lane >> 3;
    const int qt = blockIdx.x, h = blockIdx.y, b = blockIdx.z;
    const int q0 = qt * 64;

    #pragma unroll
    for (int i = 0; i < 4; i++) {
        int idx = tid + i * 128;
        int r = idx >> 3, ch = idx & 7;
        const __half* src = g_Q16
            + (size_t)(b * SEQL + q0 + r) * DMODEL + h * HDIM + ch * 8;
        cpa16(sb + (uint32_t)r * 128u + (uint32_t)((ch ^ (r & 7)) << 4), src);
    }
    const int kt_lo = (qt >= 4) ? qt - 4 : 0;
    stage_kv(sb, 0, b, h, kt_lo * 64, tid);
    CP_COMMIT(); CP_WAIT(0);
    __syncthreads();

    uint32_t qh[4][4];
    #pragma unroll
    for (int k16 = 0; k16 < 4; k16++) {
        int row = wid * 16 + r8 + (g8 & 1) * 8;
        int ch  = k16 * 2 + (g8 >> 1);
        ldmx4(sb + (uint32_t)row * 128u + (uint32_t)((ch ^ (row & 7)) << 4), qh[k16]);
    }

    float o[8][4];
    #pragma unroll
    for (int ni = 0; ni < 8; ni++)
        #pragma unroll
        for (int c = 0; c < 4; c++) o[ni][c] = 0.0f;
    float l0 = 0.0f, l1 = 0.0f;

    for (int kt = kt_lo; kt <= qt; kt++) {
        const int s = (kt - kt_lo) & 1;
        if (kt < qt) { stage_kv(sb, s ^ 1, b, h, (kt + 1) * 64, tid); CP_COMMIT(); }
        const uint32_t kb = sb + 8192u + (uint32_t)s * 16384u;

        float sc[8][4];
        #pragma unroll
        for (int ni = 0; ni < 8; ni++)
            #pragma unroll
            for (int c = 0; c < 4; c++) sc[ni][c] = 0.0f;

        #pragma unroll
        for (int k16 = 0; k16 < 4; k16++) {
            uint32_t kh[4][4];
            #pragma unroll
            for (int ng = 0; ng < 4; ng++) {
                int row = ng * 16 + r8 + (g8 >> 1) * 8;
                int ch  = k16 * 2 + (g8 & 1);
                ldmx4(kb + (uint32_t)row * 128u + (uint32_t)((ch ^ (row & 7)) << 4), kh[ng]);
            }
            #pragma unroll
            for (int ng = 0; ng < 4; ng++)
                #pragma unroll
                for (int hf = 0; hf < 2; hf++)
                    mma16816(sc[ng * 2 + hf], qh[k16], &kh[ng][hf * 2]);
        }

        const int k0 = kt * 64;
        if (kt == qt || (qt >= 4 && kt == qt - 4)) {
            const bool diag = (kt == qt);
            const int qr0 = q0 + wid * 16 + (lane >> 2);
            #pragma unroll
            for (int ni = 0; ni < 8; ni++) {
                int kj = k0 + ni * 8 + 2 * (lane & 3);
                #pragma unroll
                for (int c = 0; c < 4; c++) {
                    int kcol = kj + (c & 1), qrow = qr0 + (c >> 1) * 8;
                    bool ok = diag ? (kcol <= qrow) : (kcol >= qrow - (WINDOW - 1));
                    if (!ok) sc[ni][c] = -INFINITY;
                }
            }
        }

        #pragma unroll
        for (int ni = 0; ni < 8; ni++) {
            sc[ni][0] = ex2(sc[ni][0]);
            sc[ni][1] = ex2(sc[ni][1]);
            sc[ni][2] = ex2(sc[ni][2]);
            sc[ni][3] = ex2(sc[ni][3]);
            l0 += sc[ni][0] + sc[ni][1];
            l1 += sc[ni][2] + sc[ni][3];
        }

        uint32_t ph[4][4];
        #pragma unroll
        for (int t = 0; t < 4; t++) {
            ph[t][0] = packhf(sc[2*t][0],   sc[2*t][1]);
            ph[t][1] = packhf(sc[2*t][2],   sc[2*t][3]);
            ph[t][2] = packhf(sc[2*t+1][0], sc[2*t+1][1]);
            ph[t][3] = packhf(sc[2*t+1][2], sc[2*t+1][3]);
        }

        const uint32_t vb = kb + 8192u;
        #pragma unroll
        for (int kt16 = 0; kt16 < 4; kt16++) {
            uint32_t vh[4][4];
            #pragma unroll
            for (int ng = 0; ng < 4; ng++) {
                int row = kt16 * 16 + r8 + (g8 & 1) * 8;
                int ch  = ng * 2 + (g8 >> 1);
                ldmx4t(vb + (uint32_t)row * 128u + (uint32_t)((ch ^ (row & 7)) << 4), vh[ng]);
            }
            #pragma unroll
            for (int ng = 0; ng < 4; ng++)
                #pragma unroll
                for (int hf = 0; hf < 2; hf++)
                    mma16816(o[ng * 2 + hf], ph[kt16], &vh[ng][hf * 2]);
        }
        if (kt < qt) { CP_WAIT(0); __syncthreads(); }
    }

    l0 += __shfl_xor_sync(0xffffffffu, l0, 1);
    l0 += __shfl_xor_sync(0xffffffffu, l0, 2);
    l1 += __shfl_xor_sync(0xffffffffu, l1, 1);
    l1 += __shfl_xor_sync(0xffffffffu, l1, 2);

    const float i0 = 1.0f / l0, i1 = 1.0f / l1;
    const int row0 = q0 + wid * 16 + (lane >> 2);
    #pragma unroll
    for (int ni = 0; ni < 8; ni++) {
        int col = h * HDIM + ni * 8 + 2 * (lane & 3);
        size_t o0 = (size_t)(b * SEQL + row0) * DMODEL + col;
        *(uint32_t*)(g_C16 + o0) = packhf(o[ni][0] * i0, o[ni][1] * i0);
        *(uint32_t*)(g_C16 + o0 + 8 * DMODEL) = packhf(o[ni][2] * i1, o[ni][3] * i1);
    }
}

// ---------------------------------------------------------------------------------------
extern "C" void kernel_launch(void* const* d_in, const int* in_sizes, int n_in,
                              void* d_out, int out_size)
{
    const float* iQ = (const float*)d_in[0];
    const float* iK = (const float*)d_in[1];
    const float* iV = (const float*)d_in[2];
    const float* wQ = (const float*)d_in[3];
    const float* wK = (const float*)d_in[4];
    const float* wV = (const float*)d_in[5];
    const float* wF = (const float*)d_in[6];
    float* out = (float*)d_out;

    prep_w_kernel<<<dim3(16, 16, 4), dim3(32, 8)>>>(wQ, wK, wV, wF);

    const int gemm_smem = 2 * STGB;   // 65536
    cudaFuncSetAttribute((const void*)gemm_qkv,
                         cudaFuncAttributeMaxDynamicSharedMemorySize, gemm_smem);
    cudaFuncSetAttribute((const void*)gemm_ln,
                         cudaFuncAttributeMaxDynamicSharedMemorySize, CL_SMEM);
    cudaFuncSetAttribute((const void*)attn_tc,
                         cudaFuncAttributeMaxDynamicSharedMemorySize, 40960);

    gemm_qkv<<<dim3(4, 64, 3), 256, gemm_smem>>>(iQ, iK, iV);
    attn_tc<<<dim3(SEQL / 64, NHEAD, NB), 128, 40960>>>();
    gemm_ln<<<dim3(2, MTOT / 64), 256, CL_SMEM>>>(iQ, out);
}

// round 15
// speedup vs baseline: 1.0999x; 1.0050x over previous
#include <cuda_runtime.h>
#include <cuda_fp16.h>
#include <math.h>
#include <stdint.h>

#define NB 4
#define SEQL 2048
#define DMODEL 512
#define NHEAD 8
#define HDIM 64
#define WINDOW 256
#define MTOT (NB*SEQL)
#define XSZ ((size_t)MTOT*DMODEL)
#define WSZ ((size_t)DMODEL*DMODEL)

__device__ __align__(16) __half g_W16[4*DMODEL*DMODEL];   // W^T fp16, [w][n][k]
__device__ __align__(16) __half g_Q16[MTOT*DMODEL];       // Q has 0.125*log2e folded
__device__ __align__(16) __half g_K16[MTOT*DMODEL];
__device__ __align__(16) __half g_V16[MTOT*DMODEL];
__device__ __align__(16) __half g_C16[MTOT*DMODEL];       // ctx fp16

__device__ __forceinline__ uint32_t smem_u32(const void* p) {
    uint32_t a;
    asm("{ .reg .u64 t; cvta.to.shared.u64 t, %1; cvt.u32.u64 %0, t; }" : "=r"(a) : "l"(p));
    return a;
}
__device__ __forceinline__ void cpa16(uint32_t dst, const void* src) {
    asm volatile("cp.async.cg.shared.global [%0], [%1], 16;" :: "r"(dst), "l"(src));
}
#define CP_COMMIT() asm volatile("cp.async.commit_group;")
#define CP_WAIT(n)  asm volatile("cp.async.wait_group " #n ";")
__device__ __forceinline__ void ldmx4(uint32_t a, uint32_t* r) {
    asm volatile("ldmatrix.sync.aligned.m8n8.x4.shared.b16 {%0,%1,%2,%3}, [%4];"
                 : "=r"(r[0]), "=r"(r[1]), "=r"(r[2]), "=r"(r[3]) : "r"(a));
}
__device__ __forceinline__ void ldmx4t(uint32_t a, uint32_t* r) {
    asm volatile("ldmatrix.sync.aligned.m8n8.x4.trans.shared.b16 {%0,%1,%2,%3}, [%4];"
                 : "=r"(r[0]), "=r"(r[1]), "=r"(r[2]), "=r"(r[3]) : "r"(a));
}
__device__ __forceinline__ void mma16816(float* d, const uint32_t* a, const uint32_t* b) {
    asm volatile("mma.sync.aligned.m16n8k16.row.col.f32.f16.f16.f32 "
                 "{%0,%1,%2,%3}, {%4,%5,%6,%7}, {%8,%9}, {%0,%1,%2,%3};"
                 : "+f"(d[0]), "+f"(d[1]), "+f"(d[2]), "+f"(d[3])
                 : "r"(a[0]), "r"(a[1]), "r"(a[2]), "r"(a[3]), "r"(b[0]), "r"(b[1]));
}
__device__ __forceinline__ uint32_t packhf(float v0, float v1) {
    __half2 h = __floats2half2_rn(v0, v1);
    return *(uint32_t*)&h;
}
__device__ __forceinline__ uint32_t h2ex2(uint32_t x) {
    asm("ex2.approx.f16x2 %0, %0;" : "+r"(x));
    return x;
}
__device__ __forceinline__ uint32_t mapa_peer(uint32_t addr, uint32_t rank) {
    uint32_t r;
    asm("mapa.shared::cluster.u32 %0, %1, %2;" : "=r"(r) : "r"(addr), "r"(rank));
    return r;
}
__device__ __forceinline__ float ld_dsm(uint32_t addr) {
    float v;
    asm volatile("ld.shared::cluster.f32 %0, [%1];" : "=f"(v) : "r"(addr));
    return v;
}
#define CLUSTER_SYNC() do { \
    asm volatile("barrier.cluster.arrive.aligned;" ::: "memory"); \
    asm volatile("barrier.cluster.wait.aligned;" ::: "memory"); \
} while (0)

// ---- prep: W^T fp16 (0.125*log2e folded into W_Q) ------------------------------
__global__ __launch_bounds__(256)
void prep_w_kernel(const float* __restrict__ w0, const float* __restrict__ w1,
                   const float* __restrict__ w2, const float* __restrict__ w3)
{
    __shared__ float s[32][33];
    const int wsel = blockIdx.z;
    const float* W = (wsel == 0) ? w0 : (wsel == 1) ? w1 : (wsel == 2) ? w2 : w3;
    const float scale = (wsel == 0) ? 0.125f * 1.44269504f : 1.0f;
    const int k0 = blockIdx.x * 32, n0 = blockIdx.y * 32;
    const int tx = threadIdx.x, ty = threadIdx.y;
    #pragma unroll
    for (int i = 0; i < 4; i++)
        s[ty + 8 * i][tx] = W[(size_t)(k0 + ty + 8 * i) * DMODEL + n0 + tx];
    __syncthreads();
    const size_t base = (size_t)wsel * WSZ;
    #pragma unroll
    for (int i = 0; i < 4; i++) {
        int n = n0 + ty + 8 * i, k = k0 + tx;
        g_W16[base + (size_t)n * DMODEL + k] = __float2half_rn(s[tx][ty + 8 * i] * scale);
    }
}

// ---- QKV GEMM: fp16, BK=64, 2-stage; A loaded fp32 directly (unchanged) ----------
#define STGB 32768
__global__ __launch_bounds__(256)
void gemm_qkv(const float* __restrict__ x0, const float* __restrict__ x1,
              const float* __restrict__ x2)
{
    extern __shared__ char dyn[];
    const uint32_t sbu = smem_u32(dyn);
    const int tid = threadIdx.x, wid = tid >> 5, lane = tid & 31;
    const int wm = wid & 1, wn = wid >> 1;
    const int g8 = lane >> 3, r8 = lane & 7;
    const int bx = blockIdx.x, by = blockIdx.y;
    const int wsel = blockIdx.z;
    const float* X = (wsel == 0) ? x0 : (wsel == 1) ? x1 : x2;
    const __half* Bp = g_W16 + (size_t)wsel * WSZ;
    const int arow = by * 128, brow = bx * 128;

    float4 areg[4][2];
    auto ldgA = [&](int k0) {
        #pragma unroll
        for (int i = 0; i < 4; i++) {
            int idx = tid + i * 256;
            int r = idx >> 3, ch = idx & 7;
            const float* src = X + (size_t)(arow + r) * DMODEL + k0 + ch * 8;
            areg[i][0] = *(const float4*)src;
            areg[i][1] = *(const float4*)(src + 4);
        }
    };
    auto stsA = [&](int s) {
        #pragma unroll
        for (int i = 0; i < 4; i++) {
            int idx = tid + i * 256;
            int r = idx >> 3, ch = idx & 7;
            uint4 p;
            p.x = packhf(areg[i][0].x, areg[i][0].y);
            p.y = packhf(areg[i][0].z, areg[i][0].w);
            p.z = packhf(areg[i][1].x, areg[i][1].y);
            p.w = packhf(areg[i][1].z, areg[i][1].w);
            *(uint4*)(dyn + s * STGB + r * 128 + ((ch ^ (r & 7)) << 4)) = p;
        }
    };
    auto cpaB = [&](int s, int k0) {
        uint32_t base = sbu + (uint32_t)s * STGB + 16384u;
        #pragma unroll
        for (int i = 0; i < 4; i++) {
            int idx = tid + i * 256;
            int r = idx >> 3, ch = idx & 7;
            cpa16(base + (uint32_t)r * 128u + (uint32_t)((ch ^ (r & 7)) << 4),
                  Bp + (size_t)(brow + r) * DMODEL + k0 + ch * 8);
        }
    };

    float d[4][4][4];
    #pragma unroll
    for (int mi = 0; mi < 4; mi++)
        #pragma unroll
        for (int ni = 0; ni < 4; ni++)
            #pragma unroll
            for (int q = 0; q < 4; q++) d[mi][ni][q] = 0.0f;

    ldgA(0); stsA(0); cpaB(0, 0); CP_COMMIT();

    for (int c = 0; c < 8; c++) {
        if (c < 7) {
            ldgA((c + 1) * 64);
            cpaB((c + 1) & 1, (c + 1) * 64);
            CP_COMMIT(); CP_WAIT(1);
        } else { CP_WAIT(0); }
        __syncthreads();

        const uint32_t ss = sbu + (uint32_t)(c & 1) * STGB;
        #pragma unroll
        for (int k16 = 0; k16 < 4; k16++) {
            uint32_t ah[4][4], bh[8];
            #pragma unroll
            for (int mi = 0; mi < 4; mi++) {
                int row = wm * 64 + mi * 16 + r8 + (g8 & 1) * 8;
                int ch  = k16 * 2 + (g8 >> 1);
                ldmx4(ss + (uint32_t)row * 128u + (uint32_t)((ch ^ (row & 7)) << 4), ah[mi]);
            }
            #pragma unroll
            for (int np = 0; np < 2; np++) {
                int row = wn * 32 + np * 16 + r8 + (g8 >> 1) * 8;
                int ch  = k16 * 2 + (g8 & 1);
                ldmx4(ss + 16384u + (uint32_t)row * 128u
                         + (uint32_t)((ch ^ (row & 7)) << 4), &bh[np * 4]);
            }
            #pragma unroll
            for (int mi = 0; mi < 4; mi++)
                #pragma unroll
                for (int ni = 0; ni < 4; ni++)
                    mma16816(d[mi][ni], ah[mi], &bh[ni * 2]);
        }
        if (c < 7) stsA((c + 1) & 1);
        __syncthreads();
    }

    __half* dst = (wsel == 0) ? g_Q16 : (wsel == 1) ? g_K16 : g_V16;
    const int rbase = by * 128 + wm * 64 + (lane >> 2);
    const int cbase = bx * 128 + wn * 32 + (lane & 3) * 2;
    #pragma unroll
    for (int mi = 0; mi < 4; mi++)
        #pragma unroll
        for (int ni = 0; ni < 4; ni++) {
            int col = cbase + ni * 8;
            #pragma unroll
            for (int hf = 0; hf < 2; hf++) {
                int row = rbase + mi * 16 + hf * 8;
                *(uint32_t*)(dst + (size_t)row * DMODEL + col) =
                    packhf(d[mi][ni][hf * 2], d[mi][ni][hf * 2 + 1]);
            }
        }
}

// ---- cluster-fused out-proj + residual + LayerNorm (unchanged R14) -----------------
#define CLSTG 40960
#define CL_SMEM 84992
__global__ __launch_bounds__(256) __cluster_dims__(2, 1, 1)
void gemm_ln(const float* __restrict__ resid, float* __restrict__ out)
{
    extern __shared__ char dyn[];
    const uint32_t sb = smem_u32(dyn);
    float* red     = (float*)(dyn + 81920);
    float* redq    = (float*)(dyn + 82944);
    float* partial = (float*)(dyn + 83968);
    float* stats   = (float*)(dyn + 84480);

    const int tid = threadIdx.x, wid = tid >> 5, lane = tid & 31;
    const int wm = wid & 1, wn = wid >> 1;
    const int g8 = lane >> 3, r8 = lane & 7;
    const uint32_t bx = blockIdx.x;
    const int m0 = blockIdx.y * 64;
    const int c0 = bx * 256;
    const __half* A = g_C16;
    const __half* B = g_W16 + 3 * WSZ + (size_t)c0 * DMODEL;

    auto stage = [&](int s, int k0) {
        uint32_t sA = sb + (uint32_t)s * CLSTG;
        uint32_t sB = sA + 8192u;
        #pragma unroll
        for (int i = 0; i < 2; i++) {
            int idx = tid + i * 256;
            int r = idx >> 3, c = idx & 7;
            cpa16(sA + (uint32_t)r * 128u + (uint32_t)((c ^ (r & 7)) << 4),
                  A + (size_t)(m0 + r) * DMODEL + k0 + c * 8);
        }
        #pragma unroll
        for (int i = 0; i < 8; i++) {
            int idx = tid + i * 256;
            int r = idx >> 3, c = idx & 7;
            cpa16(sB + (uint32_t)r * 128u + (uint32_t)((c ^ (r & 7)) << 4),
                  B + (size_t)r * DMODEL + k0 + c * 8);
        }
    };

    float d[2][8][4];
    #pragma unroll
    for (int mi = 0; mi < 2; mi++)
        #pragma unroll
        for (int ni = 0; ni < 8; ni++)
            #pragma unroll
            for (int q = 0; q < 4; q++) d[mi][ni][q] = 0.0f;

    stage(0, 0); CP_COMMIT();

    for (int c = 0; c < 8; c++) {
        if (c < 7) {
            stage((c + 1) & 1, (c + 1) * 64);
            CP_COMMIT(); CP_WAIT(1);
        } else { CP_WAIT(0); }
        __syncthreads();

        const uint32_t sA = sb + (uint32_t)(c & 1) * CLSTG;
        const uint32_t sB = sA + 8192u;
        #pragma unroll
        for (int k16 = 0; k16 < 4; k16++) {
            uint32_t ah[2][4], bh[16];
            #pragma unroll
            for (int mi = 0; mi < 2; mi++) {
                int row = wm * 32 + mi * 16 + r8 + (g8 & 1) * 8;
                int ch  = k16 * 2 + (g8 >> 1);
                ldmx4(sA + (uint32_t)row * 128u + (uint32_t)((ch ^ (row & 7)) << 4), ah[mi]);
            }
            #pragma unroll
            for (int np = 0; np < 4; np++) {
                int row = wn * 64 + np * 16 + r8 + (g8 >> 1) * 8;
                int ch  = k16 * 2 + (g8 & 1);
                ldmx4(sB + (uint32_t)row * 128u + (uint32_t)((ch ^ (row & 7)) << 4),
                      &bh[np * 4]);
            }
            #pragma unroll
            for (int mi = 0; mi < 2; mi++)
                #pragma unroll
                for (int ni = 0; ni < 8; ni++)
                    mma16816(d[mi][ni], ah[mi], &bh[(ni >> 1) * 4 + (ni & 1) * 2]);
        }
        __syncthreads();
    }

    const int lrow0 = lane >> 2;
    #pragma unroll
    for (int mi = 0; mi < 2; mi++)
        #pragma unroll
        for (int hf = 0; hf < 2; hf++) {
            int lrow = wm * 32 + mi * 16 + hf * 8 + lrow0;
            int grow = m0 + lrow;
            float s = 0.0f, sq = 0.0f;
            #pragma unroll
            for (int ni = 0; ni < 8; ni++) {
                int col = c0 + wn * 64 + ni * 8 + (lane & 3) * 2;
                float2 rv = *(const float2*)(resid + (size_t)grow * DMODEL + col);
                float v0 = d[mi][ni][hf * 2]     + rv.x;
                float v1 = d[mi][ni][hf * 2 + 1] + rv.y;
                d[mi][ni][hf * 2]     = v0;
                d[mi][ni][hf * 2 + 1] = v1;
                s  += v0 + v1;
                sq += v0 * v0 + v1 * v1;
            }
            s  += __shfl_xor_sync(0xffffffffu, s, 1);
            s  += __shfl_xor_sync(0xffffffffu, s, 2);
            sq += __shfl_xor_sync(0xffffffffu, sq, 1);
            sq += __shfl_xor_sync(0xffffffffu, sq, 2);
            if ((lane & 3) == 0) {
                red [lrow * 4 + wn] = s;
                redq[lrow * 4 + wn] = sq;
            }
        }
    __syncthreads();

    if (tid < 64) {
        float s = 0.0f, sq = 0.0f;
        #pragma unroll
        for (int w = 0; w < 4; w++) { s += red[tid * 4 + w]; sq += redq[tid * 4 + w]; }
        partial[tid * 2]     = s;
        partial[tid * 2 + 1] = sq;
    }
    CLUSTER_SYNC();

    if (tid < 64) {
        uint32_t paddr = mapa_peer(sb + 83968u + (uint32_t)tid * 8u, bx ^ 1u);
        float s  = partial[tid * 2]     + ld_dsm(paddr);
        float sq = partial[tid * 2 + 1] + ld_dsm(paddr + 4u);
        float mean = s * (1.0f / DMODEL);
        float var  = sq * (1.0f / DMODEL) - mean * mean;
        stats[tid * 2]     = mean;
        stats[tid * 2 + 1] = rsqrtf(var + 1e-5f);
    }
    __syncthreads();

    #pragma unroll
    for (int mi = 0; mi < 2; mi++)
        #pragma unroll
        for (int hf = 0; hf < 2; hf++) {
            int lrow = wm * 32 + mi * 16 + hf * 8 + lrow0;
            float mean = stats[lrow * 2], rstd = stats[lrow * 2 + 1];
            int grow = m0 + lrow;
            #pragma unroll
            for (int ni = 0; ni < 8; ni++) {
                int col = c0 + wn * 64 + ni * 8 + (lane & 3) * 2;
                float v0 = (d[mi][ni][hf * 2]     - mean) * rstd;
                float v1 = (d[mi][ni][hf * 2 + 1] - mean) * rstd;
                *(float2*)(out + (size_t)grow * DMODEL + col) = make_float2(v0, v1);
            }
        }
}

// ---- attention: fp16 flash, banded; f16x2 exp + tensor-core row sums ----------------
__device__ __forceinline__ void stage_kv(uint32_t sb, int s, int b, int h,
                                         int krow0, int tid)
{
    const uint32_t base = sb + 8192u + (uint32_t)s * 16384u;
    #pragma unroll
    for (int i = 0; i < 8; i++) {
        int idx = tid + i * 128;
        int mat = idx >> 9, rem = idx & 511;
        int r = rem >> 3, ch = rem & 7;
        const __half* src = (mat ? g_V16 : g_K16)
            + (size_t)(b * SEQL + krow0 + r) * DMODEL + h * HDIM + ch * 8;
        cpa16(base + (uint32_t)mat * 8192u + (uint32_t)r * 128u
                   + (uint32_t)((ch ^ (r & 7)) << 4), src);
    }
}

__global__ __launch_bounds__(128, 3)
void attn_tc()
{
    extern __shared__ char dyn[];
    const uint32_t sb = smem_u32(dyn);
    const int tid = threadIdx.x, wid = tid >> 5, lane = tid & 31;
    const int r8 = lane & 7, g8 = lane >> 3;
    const int qt = blockIdx.x, h = blockIdx.y, b = blockIdx.z;
    const int q0 = qt * 64;

    #pragma unroll
    for (int i = 0; i < 4; i++) {
        int idx = tid + i * 128;
        int r = idx >> 3, ch = idx & 7;
        const __half* src = g_Q16
            + (size_t)(b * SEQL + q0 + r) * DMODEL + h * HDIM + ch * 8;
        cpa16(sb + (uint32_t)r * 128u + (uint32_t)((ch ^ (r & 7)) << 4), src);
    }
    const int kt_lo = (qt >= 4) ? qt - 4 : 0;
    stage_kv(sb, 0, b, h, kt_lo * 64, tid);
    CP_COMMIT(); CP_WAIT(0);
    __syncthreads();

    uint32_t qh[4][4];
    #pragma unroll
    for (int k16 = 0; k16 < 4; k16++) {
        int row = wid * 16 + r8 + (g8 & 1) * 8;
        int ch  = k16 * 2 + (g8 >> 1);
        ldmx4(sb + (uint32_t)row * 128u + (uint32_t)((ch ^ (row & 7)) << 4), qh[k16]);
    }

    float o[8][4], lsum[4];
    #pragma unroll
    for (int ni = 0; ni < 8; ni++)
        #pragma unroll
        for (int c = 0; c < 4; c++) o[ni][c] = 0.0f;
    #pragma unroll
    for (int c = 0; c < 4; c++) lsum[c] = 0.0f;

    const uint32_t bones[2] = {0x3C003C00u, 0x3C003C00u};   // fp16 ones

    for (int kt = kt_lo; kt <= qt; kt++) {
        const int s = (kt - kt_lo) & 1;
        if (kt < qt) { stage_kv(sb, s ^ 1, b, h, (kt + 1) * 64, tid); CP_COMMIT(); }
        const uint32_t kb = sb + 8192u + (uint32_t)s * 16384u;

        float sc[8][4];
        #pragma unroll
        for (int ni = 0; ni < 8; ni++)
            #pragma unroll
            for (int c = 0; c < 4; c++) sc[ni][c] = 0.0f;

        #pragma unroll
        for (int k16 = 0; k16 < 4; k16++) {
            uint32_t kh[4][4];
            #pragma unroll
            for (int ng = 0; ng < 4; ng++) {
                int row = ng * 16 + r8 + (g8 >> 1) * 8;
                int ch  = k16 * 2 + (g8 & 1);
                ldmx4(kb + (uint32_t)row * 128u + (uint32_t)((ch ^ (row & 7)) << 4), kh[ng]);
            }
            #pragma unroll
            for (int ng = 0; ng < 4; ng++)
                #pragma unroll
                for (int hf = 0; hf < 2; hf++)
                    mma16816(sc[ng * 2 + hf], qh[k16], &kh[ng][hf * 2]);
        }

        const int k0 = kt * 64;
        if (kt == qt || (qt >= 4 && kt == qt - 4)) {
            const bool diag = (kt == qt);
            const int qr0 = q0 + wid * 16 + (lane >> 2);
            #pragma unroll
            for (int ni = 0; ni < 8; ni++) {
                int kj = k0 + ni * 8 + 2 * (lane & 3);
                #pragma unroll
                for (int c = 0; c < 4; c++) {
                    int kcol = kj + (c & 1), qrow = qr0 + (c >> 1) * 8;
                    bool ok = diag ? (kcol <= qrow) : (kcol >= qrow - (WINDOW - 1));
                    if (!ok) sc[ni][c] = -INFINITY;
                }
            }
        }

        // P = exp2(S) computed directly in fp16x2 (pack then MUFU.EX2 f16x2)
        uint32_t ph[4][4];
        #pragma unroll
        for (int t = 0; t < 4; t++) {
            ph[t][0] = h2ex2(packhf(sc[2*t][0],   sc[2*t][1]));
            ph[t][1] = h2ex2(packhf(sc[2*t][2],   sc[2*t][3]));
            ph[t][2] = h2ex2(packhf(sc[2*t+1][0], sc[2*t+1][1]));
            ph[t][3] = h2ex2(packhf(sc[2*t+1][2], sc[2*t+1][3]));
        }

        const uint32_t vb = kb + 8192u;
        #pragma unroll
        for (int kt16 = 0; kt16 < 4; kt16++) {
            uint32_t vh[4][4];
            #pragma unroll
            for (int ng = 0; ng < 4; ng++) {
                int row = kt16 * 16 + r8 + (g8 & 1) * 8;
                int ch  = ng * 2 + (g8 >> 1);
                ldmx4t(vb + (uint32_t)row * 128u + (uint32_t)((ch ^ (row & 7)) << 4), vh[ng]);
            }
            mma16816(lsum, ph[kt16], bones);   // row sums via tensor core
            #pragma unroll
            for (int ng = 0; ng < 4; ng++)
                #pragma unroll
                for (int hf = 0; hf < 2; hf++)
                    mma16816(o[ng * 2 + hf], ph[kt16], &vh[ng][hf * 2]);
        }
        if (kt < qt) { CP_WAIT(0); __syncthreads(); }
    }

    const float i0 = 1.0f / lsum[0], i1 = 1.0f / lsum[2];
    const int row0 = q0 + wid * 16 + (lane >> 2);
    #pragma unroll
    for (int ni = 0; ni < 8; ni++) {
        int col = h * HDIM + ni * 8 + 2 * (lane & 3);
        size_t o0 = (size_t)(b * SEQL + row0) * DMODEL + col;
        *(uint32_t*)(g_C16 + o0) = packhf(o[ni][0] * i0, o[ni][1] * i0);
        *(uint32_t*)(g_C16 + o0 + 8 * DMODEL) = packhf(o[ni][2] * i1, o[ni][3] * i1);
    }
}

// ---------------------------------------------------------------------------------------
extern "C" void kernel_launch(void* const* d_in, const int* in_sizes, int n_in,
                              void* d_out, int out_size)
{
    const float* iQ = (const float*)d_in[0];
    const float* iK = (const float*)d_in[1];
    const float* iV = (const float*)d_in[2];
    const float* wQ = (const float*)d_in[3];
    const float* wK = (const float*)d_in[4];
    const float* wV = (const float*)d_in[5];
    const float* wF = (const float*)d_in[6];
    float* out = (float*)d_out;

    prep_w_kernel<<<dim3(16, 16, 4), dim3(32, 8)>>>(wQ, wK, wV, wF);

    const int gemm_smem = 2 * STGB;   // 65536
    cudaFuncSetAttribute((const void*)gemm_qkv,
                         cudaFuncAttributeMaxDynamicSharedMemorySize, gemm_smem);
    cudaFuncSetAttribute((const void*)gemm_ln,
                         cudaFuncAttributeMaxDynamicSharedMemorySize, CL_SMEM);
    cudaFuncSetAttribute((const void*)attn_tc,
                         cudaFuncAttributeMaxDynamicSharedMemorySize, 40960);

    gemm_qkv<<<dim3(4, 64, 3), 256, gemm_smem>>>(iQ, iK, iV);
    attn_tc<<<dim3(SEQL / 64, NHEAD, NB), 128, 40960>>>();
    gemm_ln<<<dim3(2, MTOT / 64), 256, CL_SMEM>>>(iQ, out);
}

// round 16
// speedup vs baseline: 1.1461x; 1.0420x over previous
#include <cuda_runtime.h>
#include <cuda_fp16.h>
#include <math.h>
#include <stdint.h>

#define NB 4
#define SEQL 2048
#define DMODEL 512
#define NHEAD 8
#define HDIM 64
#define WINDOW 256
#define MTOT (NB*SEQL)
#define XSZ ((size_t)MTOT*DMODEL)
#define WSZ ((size_t)DMODEL*DMODEL)

__device__ __align__(16) __half g_W16[4*DMODEL*DMODEL];   // W^T fp16, [w][n][k]
__device__ __align__(16) __half g_Q16[MTOT*DMODEL];       // Q has 0.125*log2e folded
__device__ __align__(16) __half g_K16[MTOT*DMODEL];
__device__ __align__(16) __half g_V16[MTOT*DMODEL];
__device__ __align__(16) __half g_C16[MTOT*DMODEL];       // ctx fp16

__device__ __forceinline__ uint32_t smem_u32(const void* p) {
    uint32_t a;
    asm("{ .reg .u64 t; cvta.to.shared.u64 t, %1; cvt.u32.u64 %0, t; }" : "=r"(a) : "l"(p));
    return a;
}
__device__ __forceinline__ void cpa16(uint32_t dst, const void* src) {
    asm volatile("cp.async.cg.shared.global [%0], [%1], 16;" :: "r"(dst), "l"(src));
}
#define CP_COMMIT() asm volatile("cp.async.commit_group;")
#define CP_WAIT(n)  asm volatile("cp.async.wait_group " #n ";")
__device__ __forceinline__ void ldmx4(uint32_t a, uint32_t* r) {
    asm volatile("ldmatrix.sync.aligned.m8n8.x4.shared.b16 {%0,%1,%2,%3}, [%4];"
                 : "=r"(r[0]), "=r"(r[1]), "=r"(r[2]), "=r"(r[3]) : "r"(a));
}
__device__ __forceinline__ void ldmx4t(uint32_t a, uint32_t* r) {
    asm volatile("ldmatrix.sync.aligned.m8n8.x4.trans.shared.b16 {%0,%1,%2,%3}, [%4];"
                 : "=r"(r[0]), "=r"(r[1]), "=r"(r[2]), "=r"(r[3]) : "r"(a));
}
__device__ __forceinline__ void mma16816(float* d, const uint32_t* a, const uint32_t* b) {
    asm volatile("mma.sync.aligned.m16n8k16.row.col.f32.f16.f16.f32 "
                 "{%0,%1,%2,%3}, {%4,%5,%6,%7}, {%8,%9}, {%0,%1,%2,%3};"
                 : "+f"(d[0]), "+f"(d[1]), "+f"(d[2]), "+f"(d[3])
                 : "r"(a[0]), "r"(a[1]), "r"(a[2]), "r"(a[3]), "r"(b[0]), "r"(b[1]));
}
__device__ __forceinline__ uint32_t packhf(float v0, float v1) {
    __half2 h = __floats2half2_rn(v0, v1);
    return *(uint32_t*)&h;
}
__device__ __forceinline__ uint32_t h2ex2(uint32_t x) {
    asm("ex2.approx.f16x2 %0, %0;" : "+r"(x));
    return x;
}
__device__ __forceinline__ uint32_t mapa_peer(uint32_t addr, uint32_t rank) {
    uint32_t r;
    asm("mapa.shared::cluster.u32 %0, %1, %2;" : "=r"(r) : "r"(addr), "r"(rank));
    return r;
}
__device__ __forceinline__ float ld_dsm(uint32_t addr) {
    float v;
    asm volatile("ld.shared::cluster.f32 %0, [%1];" : "=f"(v) : "r"(addr));
    return v;
}
#define CLUSTER_SYNC() do { \
    asm volatile("barrier.cluster.arrive.aligned;" ::: "memory"); \
    asm volatile("barrier.cluster.wait.aligned;" ::: "memory"); \
} while (0)

// ---- prep: W^T fp16 (0.125*log2e folded into W_Q) ------------------------------
__global__ __launch_bounds__(256)
void prep_w_kernel(const float* __restrict__ w0, const float* __restrict__ w1,
                   const float* __restrict__ w2, const float* __restrict__ w3)
{
    __shared__ float s[32][33];
    const int wsel = blockIdx.z;
    const float* W = (wsel == 0) ? w0 : (wsel == 1) ? w1 : (wsel == 2) ? w2 : w3;
    const float scale = (wsel == 0) ? 0.125f * 1.44269504f : 1.0f;
    const int k0 = blockIdx.x * 32, n0 = blockIdx.y * 32;
    const int tx = threadIdx.x, ty = threadIdx.y;
    #pragma unroll
    for (int i = 0; i < 4; i++)
        s[ty + 8 * i][tx] = W[(size_t)(k0 + ty + 8 * i) * DMODEL + n0 + tx];
    __syncthreads();
    const size_t base = (size_t)wsel * WSZ;
    #pragma unroll
    for (int i = 0; i < 4; i++) {
        int n = n0 + ty + 8 * i, k = k0 + tx;
        g_W16[base + (size_t)n * DMODEL + k] = __float2half_rn(s[tx][ty + 8 * i] * scale);
    }
}

// ---- QKV GEMM: 64x128 CTA tile, 128 threads, 4 CTAs/SM, BK=64, 2-stage -----------
// stage (24KB): A 64x128B @0 (8KB), B 128x128B @8192 (16KB)
#define QSTG 24576
__global__ __launch_bounds__(128, 4)
void gemm_qkv(const float* __restrict__ x0, const float* __restrict__ x1,
              const float* __restrict__ x2)
{
    extern __shared__ char dyn[];
    const uint32_t sbu = smem_u32(dyn);
    const int tid = threadIdx.x, wid = tid >> 5, lane = tid & 31;
    const int wm = wid & 1, wn = wid >> 1;          // 2x2 warp grid
    const int g8 = lane >> 3, r8 = lane & 7;
    const int bx = blockIdx.x, by = blockIdx.y;
    const int wsel = blockIdx.z;
    const float* X = (wsel == 0) ? x0 : (wsel == 1) ? x1 : x2;
    const __half* Bp = g_W16 + (size_t)wsel * WSZ;
    const int arow = by * 64, brow = bx * 128;

    float4 areg[4][2];
    auto ldgA = [&](int k0) {
        #pragma unroll
        for (int i = 0; i < 4; i++) {
            int idx = tid + i * 128;
            int r = idx >> 3, ch = idx & 7;
            const float* src = X + (size_t)(arow + r) * DMODEL + k0 + ch * 8;
            areg[i][0] = *(const float4*)src;
            areg[i][1] = *(const float4*)(src + 4);
        }
    };
    auto stsA = [&](int s) {
        #pragma unroll
        for (int i = 0; i < 4; i++) {
            int idx = tid + i * 128;
            int r = idx >> 3, ch = idx & 7;
            uint4 p;
            p.x = packhf(areg[i][0].x, areg[i][0].y);
            p.y = packhf(areg[i][0].z, areg[i][0].w);
            p.z = packhf(areg[i][1].x, areg[i][1].y);
            p.w = packhf(areg[i][1].z, areg[i][1].w);
            *(uint4*)(dyn + s * QSTG + r * 128 + ((ch ^ (r & 7)) << 4)) = p;
        }
    };
    auto cpaB = [&](int s, int k0) {
        uint32_t base = sbu + (uint32_t)s * QSTG + 8192u;
        #pragma unroll
        for (int i = 0; i < 8; i++) {
            int idx = tid + i * 128;
            int r = idx >> 3, ch = idx & 7;
            cpa16(base + (uint32_t)r * 128u + (uint32_t)((ch ^ (r & 7)) << 4),
                  Bp + (size_t)(brow + r) * DMODEL + k0 + ch * 8);
        }
    };

    float d[2][8][4];
    #pragma unroll
    for (int mi = 0; mi < 2; mi++)
        #pragma unroll
        for (int ni = 0; ni < 8; ni++)
            #pragma unroll
            for (int q = 0; q < 4; q++) d[mi][ni][q] = 0.0f;

    ldgA(0); stsA(0); cpaB(0, 0); CP_COMMIT();

    for (int c = 0; c < 8; c++) {
        if (c < 7) {
            ldgA((c + 1) * 64);
            cpaB((c + 1) & 1, (c + 1) * 64);
            CP_COMMIT(); CP_WAIT(1);
        } else { CP_WAIT(0); }
        __syncthreads();

        const uint32_t sA = sbu + (uint32_t)(c & 1) * QSTG;
        const uint32_t sB = sA + 8192u;
        #pragma unroll
        for (int k16 = 0; k16 < 4; k16++) {
            uint32_t ah[2][4], bh[16];
            #pragma unroll
            for (int mi = 0; mi < 2; mi++) {
                int row = wm * 32 + mi * 16 + r8 + (g8 & 1) * 8;
                int ch  = k16 * 2 + (g8 >> 1);
                ldmx4(sA + (uint32_t)row * 128u + (uint32_t)((ch ^ (row & 7)) << 4), ah[mi]);
            }
            #pragma unroll
            for (int np = 0; np < 4; np++) {
                int row = wn * 64 + np * 16 + r8 + (g8 >> 1) * 8;
                int ch  = k16 * 2 + (g8 & 1);
                ldmx4(sB + (uint32_t)row * 128u + (uint32_t)((ch ^ (row & 7)) << 4),
                      &bh[np * 4]);
            }
            #pragma unroll
            for (int mi = 0; mi < 2; mi++)
                #pragma unroll
                for (int ni = 0; ni < 8; ni++)
                    mma16816(d[mi][ni], ah[mi], &bh[(ni >> 1) * 4 + (ni & 1) * 2]);
        }
        if (c < 7) stsA((c + 1) & 1);
        __syncthreads();
    }

    __half* dst = (wsel == 0) ? g_Q16 : (wsel == 1) ? g_K16 : g_V16;
    const int rbase = by * 64 + wm * 32 + (lane >> 2);
    const int cbase = bx * 128 + wn * 64 + (lane & 3) * 2;
    #pragma unroll
    for (int mi = 0; mi < 2; mi++)
        #pragma unroll
        for (int ni = 0; ni < 8; ni++) {
            int col = cbase + ni * 8;
            #pragma unroll
            for (int hf = 0; hf < 2; hf++) {
                int row = rbase + mi * 16 + hf * 8;
                *(uint32_t*)(dst + (size_t)row * DMODEL + col) =
                    packhf(d[mi][ni][hf * 2], d[mi][ni][hf * 2 + 1]);
            }
        }
}

// ---- cluster-fused out-proj + residual + LayerNorm (unchanged R14) -----------------
#define CLSTG 40960
#define CL_SMEM 84992
__global__ __launch_bounds__(256) __cluster_dims__(2, 1, 1)
void gemm_ln(const float* __restrict__ resid, float* __restrict__ out)
{
    extern __shared__ char dyn[];
    const uint32_t sb = smem_u32(dyn);
    float* red     = (float*)(dyn + 81920);
    float* redq    = (float*)(dyn + 82944);
    float* partial = (float*)(dyn + 83968);
    float* stats   = (float*)(dyn + 84480);

    const int tid = threadIdx.x, wid = tid >> 5, lane = tid & 31;
    const int wm = wid & 1, wn = wid >> 1;
    const int g8 = lane >> 3, r8 = lane & 7;
    const uint32_t bx = blockIdx.x;
    const int m0 = blockIdx.y * 64;
    const int c0 = bx * 256;
    const __half* A = g_C16;
    const __half* B = g_W16 + 3 * WSZ + (size_t)c0 * DMODEL;

    auto stage = [&](int s, int k0) {
        uint32_t sA = sb + (uint32_t)s * CLSTG;
        uint32_t sB = sA + 8192u;
        #pragma unroll
        for (int i = 0; i < 2; i++) {
            int idx = tid + i * 256;
            int r = idx >> 3, c = idx & 7;
            cpa16(sA + (uint32_t)r * 128u + (uint32_t)((c ^ (r & 7)) << 4),
                  A + (size_t)(m0 + r) * DMODEL + k0 + c * 8);
        }
        #pragma unroll
        for (int i = 0; i < 8; i++) {
            int idx = tid + i * 256;
            int r = idx >> 3, c = idx & 7;
            cpa16(sB + (uint32_t)r * 128u + (uint32_t)((c ^ (r & 7)) << 4),
                  B + (size_t)r * DMODEL + k0 + c * 8);
        }
    };

    float d[2][8][4];
    #pragma unroll
    for (int mi = 0; mi < 2; mi++)
        #pragma unroll
        for (int ni = 0; ni < 8; ni++)
            #pragma unroll
            for (int q = 0; q < 4; q++) d[mi][ni][q] = 0.0f;

    stage(0, 0); CP_COMMIT();

    for (int c = 0; c < 8; c++) {
        if (c < 7) {
            stage((c + 1) & 1, (c + 1) * 64);
            CP_COMMIT(); CP_WAIT(1);
        } else { CP_WAIT(0); }
        __syncthreads();

        const uint32_t sA = sb + (uint32_t)(c & 1) * CLSTG;
        const uint32_t sB = sA + 8192u;
        #pragma unroll
        for (int k16 = 0; k16 < 4; k16++) {
            uint32_t ah[2][4], bh[16];
            #pragma unroll
            for (int mi = 0; mi < 2; mi++) {
                int row = wm * 32 + mi * 16 + r8 + (g8 & 1) * 8;
                int ch  = k16 * 2 + (g8 >> 1);
                ldmx4(sA + (uint32_t)row * 128u + (uint32_t)((ch ^ (row & 7)) << 4), ah[mi]);
            }
            #pragma unroll
            for (int np = 0; np < 4; np++) {
                int row = wn * 64 + np * 16 + r8 + (g8 >> 1) * 8;
                int ch  = k16 * 2 + (g8 & 1);
                ldmx4(sB + (uint32_t)row * 128u + (uint32_t)((ch ^ (row & 7)) << 4),
                      &bh[np * 4]);
            }
            #pragma unroll
            for (int mi = 0; mi < 2; mi++)
                #pragma unroll
                for (int ni = 0; ni < 8; ni++)
                    mma16816(d[mi][ni], ah[mi], &bh[(ni >> 1) * 4 + (ni & 1) * 2]);
        }
        __syncthreads();
    }

    const int lrow0 = lane >> 2;
    #pragma unroll
    for (int mi = 0; mi < 2; mi++)
        #pragma unroll
        for (int hf = 0; hf < 2; hf++) {
            int lrow = wm * 32 + mi * 16 + hf * 8 + lrow0;
            int grow = m0 + lrow;
            float s = 0.0f, sq = 0.0f;
            #pragma unroll
            for (int ni = 0; ni < 8; ni++) {
                int col = c0 + wn * 64 + ni * 8 + (lane & 3) * 2;
                float2 rv = *(const float2*)(resid + (size_t)grow * DMODEL + col);
                float v0 = d[mi][ni][hf * 2]     + rv.x;
                float v1 = d[mi][ni][hf * 2 + 1] + rv.y;
                d[mi][ni][hf * 2]     = v0;
                d[mi][ni][hf * 2 + 1] = v1;
                s  += v0 + v1;
                sq += v0 * v0 + v1 * v1;
            }
            s  += __shfl_xor_sync(0xffffffffu, s, 1);
            s  += __shfl_xor_sync(0xffffffffu, s, 2);
            sq += __shfl_xor_sync(0xffffffffu, sq, 1);
            sq += __shfl_xor_sync(0xffffffffu, sq, 2);
            if ((lane & 3) == 0) {
                red [lrow * 4 + wn] = s;
                redq[lrow * 4 + wn] = sq;
            }
        }
    __syncthreads();

    if (tid < 64) {
        float s = 0.0f, sq = 0.0f;
        #pragma unroll
        for (int w = 0; w < 4; w++) { s += red[tid * 4 + w]; sq += redq[tid * 4 + w]; }
        partial[tid * 2]     = s;
        partial[tid * 2 + 1] = sq;
    }
    CLUSTER_SYNC();

    if (tid < 64) {
        uint32_t paddr = mapa_peer(sb + 83968u + (uint32_t)tid * 8u, bx ^ 1u);
        float s  = partial[tid * 2]     + ld_dsm(paddr);
        float sq = partial[tid * 2 + 1] + ld_dsm(paddr + 4u);
        float mean = s * (1.0f / DMODEL);
        float var  = sq * (1.0f / DMODEL) - mean * mean;
        stats[tid * 2]     = mean;
        stats[tid * 2 + 1] = rsqrtf(var + 1e-5f);
    }
    __syncthreads();

    #pragma unroll
    for (int mi = 0; mi < 2; mi++)
        #pragma unroll
        for (int hf = 0; hf < 2; hf++) {
            int lrow = wm * 32 + mi * 16 + hf * 8 + lrow0;
            float mean = stats[lrow * 2], rstd = stats[lrow * 2 + 1];
            int grow = m0 + lrow;
            #pragma unroll
            for (int ni = 0; ni < 8; ni++) {
                int col = c0 + wn * 64 + ni * 8 + (lane & 3) * 2;
                float v0 = (d[mi][ni][hf * 2]     - mean) * rstd;
                float v1 = (d[mi][ni][hf * 2 + 1] - mean) * rstd;
                *(float2*)(out + (size_t)grow * DMODEL + col) = make_float2(v0, v1);
            }
        }
}

// ---- attention: fp16 flash, banded; f16x2 exp + tensor-core row sums (R15) ----------
__device__ __forceinline__ void stage_kv(uint32_t sb, int s, int b, int h,
                                         int krow0, int tid)
{
    const uint32_t base = sb + 8192u + (uint32_t)s * 16384u;
    #pragma unroll
    for (int i = 0; i < 8; i++) {
        int idx = tid + i * 128;
        int mat = idx >> 9, rem = idx & 511;
        int r = rem >> 3, ch = rem & 7;
        const __half* src = (mat ? g_V16 : g_K16)
            + (size_t)(b * SEQL + krow0 + r) * DMODEL + h * HDIM + ch * 8;
        cpa16(base + (uint32_t)mat * 8192u + (uint32_t)r * 128u
                   + (uint32_t)((ch ^ (r & 7)) << 4), src);
    }
}

__global__ __launch_bounds__(128, 3)
void attn_tc()
{
    extern __shared__ char dyn[];
    const uint32_t sb = smem_u32(dyn);
    const int tid = threadIdx.x, wid = tid >> 5, lane = tid & 31;
    const int r8 = lane & 7, g8 = lane >> 3;
    const int qt = blockIdx.x, h = blockIdx.y, b = blockIdx.z;
    const int q0 = qt * 64;

    #pragma unroll
    for (int i = 0; i < 4; i++) {
        int idx = tid + i * 128;
        int r = idx >> 3, ch = idx & 7;
        const __half* src = g_Q16
            + (size_t)(b * SEQL + q0 + r) * DMODEL + h * HDIM + ch * 8;
        cpa16(sb + (uint32_t)r * 128u + (uint32_t)((ch ^ (r & 7)) << 4), src);
    }
    const int kt_lo = (qt >= 4) ? qt - 4 : 0;
    stage_kv(sb, 0, b, h, kt_lo * 64, tid);
    CP_COMMIT(); CP_WAIT(0);
    __syncthreads();

    uint32_t qh[4][4];
    #pragma unroll
    for (int k16 = 0; k16 < 4; k16++) {
        int row = wid * 16 + r8 + (g8 & 1) * 8;
        int ch  = k16 * 2 + (g8 >> 1);
        ldmx4(sb + (uint32_t)row * 128u + (uint32_t)((ch ^ (row & 7)) << 4), qh[k16]);
    }

    float o[8][4], lsum[4];
    #pragma unroll
    for (int ni = 0; ni < 8; ni++)
        #pragma unroll
        for (int c = 0; c < 4; c++) o[ni][c] = 0.0f;
    #pragma unroll
    for (int c = 0; c < 4; c++) lsum[c] = 0.0f;

    const uint32_t bones[2] = {0x3C003C00u, 0x3C003C00u};

    for (int kt = kt_lo; kt <= qt; kt++) {
        const int s = (kt - kt_lo) & 1;
        if (kt < qt) { stage_kv(sb, s ^ 1, b, h, (kt + 1) * 64, tid); CP_COMMIT(); }
        const uint32_t kb = sb + 8192u + (uint32_t)s * 16384u;

        float sc[8][4];
        #pragma unroll
        for (int ni = 0; ni < 8; ni++)
            #pragma unroll
            for (int c = 0; c < 4; c++) sc[ni][c] = 0.0f;

        #pragma unroll
        for (int k16 = 0; k16 < 4; k16++) {
            uint32_t kh[4][4];
            #pragma unroll
            for (int ng = 0; ng < 4; ng++) {
                int row = ng * 16 + r8 + (g8 >> 1) * 8;
                int ch  = k16 * 2 + (g8 & 1);
                ldmx4(kb + (uint32_t)row * 128u + (uint32_t)((ch ^ (row & 7)) << 4), kh[ng]);
            }
            #pragma unroll
            for (int ng = 0; ng < 4; ng++)
                #pragma unroll
                for (int hf = 0; hf < 2; hf++)
                    mma16816(sc[ng * 2 + hf], qh[k16], &kh[ng][hf * 2]);
        }

        const int k0 = kt * 64;
        if (kt == qt || (qt >= 4 && kt == qt - 4)) {
            const bool diag = (kt == qt);
            const int qr0 = q0 + wid * 16 + (lane >> 2);
            #pragma unroll
            for (int ni = 0; ni < 8; ni++) {
                int kj = k0 + ni * 8 + 2 * (lane & 3);
                #pragma unroll
                for (int c = 0; c < 4; c++) {
                    int kcol = kj + (c & 1), qrow = qr0 + (c >> 1) * 8;
                    bool ok = diag ? (kcol <= qrow) : (kcol >= qrow - (WINDOW - 1));
                    if (!ok) sc[ni][c] = -INFINITY;
                }
            }
        }

        uint32_t ph[4][4];
        #pragma unroll
        for (int t = 0; t < 4; t++) {
            ph[t][0] = h2ex2(packhf(sc[2*t][0],   sc[2*t][1]));
            ph[t][1] = h2ex2(packhf(sc[2*t][2],   sc[2*t][3]));
            ph[t][2] = h2ex2(packhf(sc[2*t+1][0], sc[2*t+1][1]));
            ph[t][3] = h2ex2(packhf(sc[2*t+1][2], sc[2*t+1][3]));
        }

        const uint32_t vb = kb + 8192u;
        #pragma unroll
        for (int kt16 = 0; kt16 < 4; kt16++) {
            uint32_t vh[4][4];
            #pragma unroll
            for (int ng = 0; ng < 4; ng++) {
                int row = kt16 * 16 + r8 + (g8 & 1) * 8;
                int ch  = ng * 2 + (g8 >> 1);
                ldmx4t(vb + (uint32_t)row * 128u + (uint32_t)((ch ^ (row & 7)) << 4), vh[ng]);
            }
            mma16816(lsum, ph[kt16], bones);
            #pragma unroll
            for (int ng = 0; ng < 4; ng++)
                #pragma unroll
                for (int hf = 0; hf < 2; hf++)
                    mma16816(o[ng * 2 + hf], ph[kt16], &vh[ng][hf * 2]);
        }
        if (kt < qt) { CP_WAIT(0); __syncthreads(); }
    }

    const float i0 = 1.0f / lsum[0], i1 = 1.0f / lsum[2];
    const int row0 = q0 + wid * 16 + (lane >> 2);
    #pragma unroll
    for (int ni = 0; ni < 8; ni++) {
        int col = h * HDIM + ni * 8 + 2 * (lane & 3);
        size_t o0 = (size_t)(b * SEQL + row0) * DMODEL + col;
        *(uint32_t*)(g_C16 + o0) = packhf(o[ni][0] * i0, o[ni][1] * i0);
        *(uint32_t*)(g_C16 + o0 + 8 * DMODEL) = packhf(o[ni][2] * i1, o[ni][3] * i1);
    }
}

// ---------------------------------------------------------------------------------------
extern "C" void kernel_launch(void* const* d_in, const int* in_sizes, int n_in,
                              void* d_out, int out_size)
{
    const float* iQ = (const float*)d_in[0];
    const float* iK = (const float*)d_in[1];
    const float* iV = (const float*)d_in[2];
    const float* wQ = (const float*)d_in[3];
    const float* wK = (const float*)d_in[4];
    const float* wV = (const float*)d_in[5];
    const float* wF = (const float*)d_in[6];
    float* out = (float*)d_out;

    prep_w_kernel<<<dim3(16, 16, 4), dim3(32, 8)>>>(wQ, wK, wV, wF);

    const int qkv_smem = 2 * QSTG;   // 49152
    cudaFuncSetAttribute((const void*)gemm_qkv,
                         cudaFuncAttributeMaxDynamicSharedMemorySize, qkv_smem);
    cudaFuncSetAttribute((const void*)gemm_ln,
                         cudaFuncAttributeMaxDynamicSharedMemorySize, CL_SMEM);
    cudaFuncSetAttribute((const void*)attn_tc,
                         cudaFuncAttributeMaxDynamicSharedMemorySize, 40960);

    gemm_qkv<<<dim3(4, 128, 3), 128, qkv_smem>>>(iQ, iK, iV);
    attn_tc<<<dim3(SEQL / 64, NHEAD, NB), 128, 40960>>>();
    gemm_ln<<<dim3(2, MTOT / 64), 256, CL_SMEM>>>(iQ, out);
}